// round 3
// baseline (speedup 1.0000x reference)
#include <cuda_runtime.h>
#include <math.h>

#define B_ 8
#define C_ 256
#define N_ 4096
#define O_ 128

// Scratch (allocation-free rule: __device__ globals). 4 x 16MB = 64MB.
__device__ float d_theta[(size_t)B_ * N_ * O_];
__device__ float d_phi[(size_t)B_ * N_ * O_];
__device__ float d_gv[(size_t)B_ * N_ * O_];
__device__ float d_y[(size_t)B_ * N_ * O_];

// ---------------------------------------------------------------------------
// Kernel 1: channel projections.  out[b][n][o] = sum_c W[o][c]*x[b][c][n] + bias[o]
// grid (32 n-tiles, 8 batch, 3 projections), 256 threads, 128x128 tile, K=256.
// ---------------------------------------------------------------------------
__global__ __launch_bounds__(256) void proj_kernel(
    const float* __restrict__ x,
    const float* __restrict__ wt, const float* __restrict__ bt,
    const float* __restrict__ wp, const float* __restrict__ bp,
    const float* __restrict__ wg, const float* __restrict__ bg)
{
    __shared__ float xs[32][132];   // xs[c_local][n]
    __shared__ float ws[32][132];   // ws[c_local][o]  (W transposed)

    const int b  = blockIdx.y;
    const int n0 = blockIdx.x * 128;
    const float* W; const float* bias; float* out;
    if (blockIdx.z == 0)      { W = wt; bias = bt; out = d_theta; }
    else if (blockIdx.z == 1) { W = wp; bias = bp; out = d_phi;   }
    else                      { W = wg; bias = bg; out = d_gv;    }

    const int tid = threadIdx.x;
    const int tx = tid & 15;   // o direction
    const int ty = tid >> 4;   // n direction

    float acc[8][8];
#pragma unroll
    for (int i = 0; i < 8; i++)
#pragma unroll
        for (int j = 0; j < 8; j++) acc[i][j] = 0.f;

    for (int c0 = 0; c0 < C_; c0 += 32) {
        __syncthreads();
        // x chunk: [32 c][128 n], coalesced, float4 smem writes
#pragma unroll
        for (int r = 0; r < 4; r++) {
            int idx = tid + r * 256;           // 1024 float4s
            int cc = idx >> 5;
            int nv = (idx & 31) << 2;
            float4 v = *(const float4*)(x + ((size_t)(b * C_ + c0 + cc)) * N_ + n0 + nv);
            *(float4*)&xs[cc][nv] = v;
        }
        // W chunk: read W[o][c] coalesced along c, store transposed ws[c][o]
#pragma unroll
        for (int r = 0; r < 4; r++) {
            int idx = tid + r * 256;
            int o  = idx >> 3;
            int cv = (idx & 7) << 2;
            float4 w = *(const float4*)(W + (size_t)o * C_ + c0 + cv);
            ws[cv + 0][o] = w.x;
            ws[cv + 1][o] = w.y;
            ws[cv + 2][o] = w.z;
            ws[cv + 3][o] = w.w;
        }
        __syncthreads();
#pragma unroll
        for (int cc = 0; cc < 32; cc++) {
            float a[8];
#pragma unroll
            for (int i = 0; i < 8; i++) a[i] = xs[cc][ty * 8 + i];
            float4 u = *(const float4*)&ws[cc][tx * 8];
            float4 v = *(const float4*)&ws[cc][tx * 8 + 4];
            float bb[8] = {u.x, u.y, u.z, u.w, v.x, v.y, v.z, v.w};
#pragma unroll
            for (int i = 0; i < 8; i++)
#pragma unroll
                for (int j = 0; j < 8; j++) acc[i][j] += a[i] * bb[j];
        }
    }

    float4 bu = *(const float4*)(bias + tx * 8);
    float4 bv = *(const float4*)(bias + tx * 8 + 4);
    float bb[8] = {bu.x, bu.y, bu.z, bu.w, bv.x, bv.y, bv.z, bv.w};
#pragma unroll
    for (int i = 0; i < 8; i++) {
        float* row = out + ((size_t)b * N_ + n0 + ty * 8 + i) * O_ + tx * 8;
        float4 o0 = make_float4(acc[i][0] + bb[0], acc[i][1] + bb[1],
                                acc[i][2] + bb[2], acc[i][3] + bb[3]);
        float4 o1 = make_float4(acc[i][4] + bb[4], acc[i][5] + bb[5],
                                acc[i][6] + bb[6], acc[i][7] + bb[7]);
        *(float4*)row = o0;
        *(float4*)(row + 4) = o1;
    }
}

// ---------------------------------------------------------------------------
// Kernel 2: flash attention.  y[b][n][o] = softmax(theta phi)(g)
// grid (32 q-tiles, 8 batch), 256 threads. Tiles: Q 128x128, K/V 128x128.
// smem: Qs[128][129] (transposed), KP union (Ks[128][132] / Pt[128][129]),
//       Vs[128][132]  -> 201216 B dynamic.
// ---------------------------------------------------------------------------
#define ATTN_SMEM ((128 * 129 + 128 * 132 + 128 * 132) * 4)

__global__ __launch_bounds__(256, 1) void attn_kernel()
{
    extern __shared__ float sm[];
    float* Qs = sm;                 // [o][q], pad 129
    float* KP = sm + 128 * 129;     // Ks: [o][k] pad 132  /  Pt: [k][q] pad 129
    float* Vs = KP + 128 * 132;     // [k][o], pad 132

    const int b  = blockIdx.y;
    const int q0 = blockIdx.x * 128;
    const float* Q = d_theta + (size_t)b * N_ * O_;
    const float* K = d_phi   + (size_t)b * N_ * O_;
    const float* V = d_gv    + (size_t)b * N_ * O_;

    const int tid = threadIdx.x;
    const int tx = tid & 15;   // k / o direction
    const int ty = tid >> 4;   // q direction

    // Load Q tile transposed: Qs[o][q]
#pragma unroll
    for (int r = 0; r < 16; r++) {
        int idx = tid + r * 256;
        int q  = idx >> 5;
        int kv = (idx & 31) << 2;
        float4 v = *(const float4*)(Q + (size_t)(q0 + q) * O_ + kv);
        Qs[(kv + 0) * 129 + q] = v.x;
        Qs[(kv + 1) * 129 + q] = v.y;
        Qs[(kv + 2) * 129 + q] = v.z;
        Qs[(kv + 3) * 129 + q] = v.w;
    }

    float acc[8][8];
    float p[8][8];
    float m[8], l[8];
#pragma unroll
    for (int i = 0; i < 8; i++) {
        m[i] = -1e30f;
        l[i] = 0.f;
#pragma unroll
        for (int j = 0; j < 8; j++) acc[i][j] = 0.f;
    }

    for (int jt = 0; jt < 32; jt++) {
        const int k0 = jt * 128;
        __syncthreads();   // previous PV done (also covers Q-load on first iter)

        // K tile transposed: Ks[o][k].  Lanes along k -> conflict-free STS,
        // strided LDG (L1 absorbs it).
#pragma unroll
        for (int r = 0; r < 16; r++) {
            int idx = tid + r * 256;
            int kq  = idx & 31;
            int grp = idx >> 5;
            int kv  = (grp & 31) << 2;
            int kb  = grp >> 5;
            int k   = kb * 32 + kq;
            float4 v = *(const float4*)(K + (size_t)(k0 + k) * O_ + kv);
            KP[(kv + 0) * 132 + k] = v.x;
            KP[(kv + 1) * 132 + k] = v.y;
            KP[(kv + 2) * 132 + k] = v.z;
            KP[(kv + 3) * 132 + k] = v.w;
        }
        // V tile natural: Vs[k][o], fully coalesced both sides
#pragma unroll
        for (int r = 0; r < 16; r++) {
            int idx = tid + r * 256;
            int k  = idx >> 5;
            int ov = (idx & 31) << 2;
            float4 v = *(const float4*)(V + (size_t)(k0 + k) * O_ + ov);
            *(float4*)&Vs[k * 132 + ov] = v;
        }
        __syncthreads();

        // S = Q K^T  (p holds logits)
#pragma unroll
        for (int i = 0; i < 8; i++)
#pragma unroll
            for (int j = 0; j < 8; j++) p[i][j] = 0.f;
#pragma unroll 4
        for (int kk = 0; kk < 128; kk++) {
            float a[8];
#pragma unroll
            for (int i = 0; i < 8; i++) a[i] = Qs[kk * 129 + ty * 8 + i];
            float4 u = *(const float4*)&KP[kk * 132 + tx * 8];
            float4 v = *(const float4*)&KP[kk * 132 + tx * 8 + 4];
            float bb[8] = {u.x, u.y, u.z, u.w, v.x, v.y, v.z, v.w};
#pragma unroll
            for (int i = 0; i < 8; i++)
#pragma unroll
                for (int j = 0; j < 8; j++) p[i][j] += a[i] * bb[j];
        }

        // Online softmax update (row stats shared across the 16 tx lanes)
#pragma unroll
        for (int i = 0; i < 8; i++) {
            float rm = p[i][0];
#pragma unroll
            for (int j = 1; j < 8; j++) rm = fmaxf(rm, p[i][j]);
            rm = fmaxf(rm, __shfl_xor_sync(0xffffffffu, rm, 8));
            rm = fmaxf(rm, __shfl_xor_sync(0xffffffffu, rm, 4));
            rm = fmaxf(rm, __shfl_xor_sync(0xffffffffu, rm, 2));
            rm = fmaxf(rm, __shfl_xor_sync(0xffffffffu, rm, 1));
            float mn = fmaxf(m[i], rm);
            float sc = __expf(m[i] - mn);
            m[i] = mn;
            float rs = 0.f;
#pragma unroll
            for (int j = 0; j < 8; j++) {
                p[i][j] = __expf(p[i][j] - mn);
                rs += p[i][j];
            }
            rs += __shfl_xor_sync(0xffffffffu, rs, 8);
            rs += __shfl_xor_sync(0xffffffffu, rs, 4);
            rs += __shfl_xor_sync(0xffffffffu, rs, 2);
            rs += __shfl_xor_sync(0xffffffffu, rs, 1);
            l[i] = l[i] * sc + rs;
#pragma unroll
            for (int j = 0; j < 8; j++) acc[i][j] *= sc;
        }

        __syncthreads();   // all lanes done reading Ks
        // Write P transposed: Pt[k][q] (reuses Ks region)
#pragma unroll
        for (int i = 0; i < 8; i++)
#pragma unroll
            for (int j = 0; j < 8; j++)
                KP[(tx * 8 + j) * 129 + ty * 8 + i] = p[i][j];
        __syncthreads();

        // acc += P V
#pragma unroll 4
        for (int kk = 0; kk < 128; kk++) {
            float a[8];
#pragma unroll
            for (int i = 0; i < 8; i++) a[i] = KP[kk * 129 + ty * 8 + i];
            float4 u = *(const float4*)&Vs[kk * 132 + tx * 8];
            float4 v = *(const float4*)&Vs[kk * 132 + tx * 8 + 4];
            float bb[8] = {u.x, u.y, u.z, u.w, v.x, v.y, v.z, v.w};
#pragma unroll
            for (int i = 0; i < 8; i++)
#pragma unroll
                for (int j = 0; j < 8; j++) acc[i][j] += a[i] * bb[j];
        }
    }

    float* Y = d_y + (size_t)b * N_ * O_;
#pragma unroll
    for (int i = 0; i < 8; i++) {
        float inv = 1.f / l[i];
        float* row = Y + (size_t)(q0 + ty * 8 + i) * O_ + tx * 8;
        float4 o0 = make_float4(acc[i][0] * inv, acc[i][1] * inv,
                                acc[i][2] * inv, acc[i][3] * inv);
        float4 o1 = make_float4(acc[i][4] * inv, acc[i][5] * inv,
                                acc[i][6] * inv, acc[i][7] * inv);
        *(float4*)row = o0;
        *(float4*)(row + 4) = o1;
    }
}

// ---------------------------------------------------------------------------
// Kernel 3: out = x + BN(W_out y + b_out).  grid (32 n-tiles, 2 c-tiles, 8 b).
// Tile 128c x 128n, K = O = 128 (single chunk).
// ---------------------------------------------------------------------------
#define OUT_SMEM (2 * 128 * 132 * 4)

__global__ __launch_bounds__(256, 1) void out_kernel(
    const float* __restrict__ x,
    const float* __restrict__ wo, const float* __restrict__ bo,
    const float* __restrict__ gamma, const float* __restrict__ beta,
    const float* __restrict__ mean, const float* __restrict__ var,
    float* __restrict__ out)
{
    extern __shared__ float sm[];
    float* ws2 = sm;              // [o][c], pad 132
    float* ys  = sm + 128 * 132;  // [o][n], pad 132

    const int b  = blockIdx.z;
    const int c0 = blockIdx.y * 128;
    const int n0 = blockIdx.x * 128;
    const int tid = threadIdx.x;
    const int tx = tid & 15;   // n direction
    const int ty = tid >> 4;   // c direction

    // w_out[c][o] -> ws2[o][c]  (lanes along c: conflict-free STS)
#pragma unroll
    for (int r = 0; r < 16; r++) {
        int idx = tid + r * 256;
        int cq  = idx & 31;
        int grp = idx >> 5;
        int ov  = (grp & 31) << 2;
        int cb  = grp >> 5;
        int c   = cb * 32 + cq;
        float4 v = *(const float4*)(wo + (size_t)(c0 + c) * O_ + ov);
        ws2[(ov + 0) * 132 + c] = v.x;
        ws2[(ov + 1) * 132 + c] = v.y;
        ws2[(ov + 2) * 132 + c] = v.z;
        ws2[(ov + 3) * 132 + c] = v.w;
    }
    // y[n][o] -> ys[o][n]  (lanes along n)
#pragma unroll
    for (int r = 0; r < 16; r++) {
        int idx = tid + r * 256;
        int nq  = idx & 31;
        int grp = idx >> 5;
        int ov  = (grp & 31) << 2;
        int nb  = grp >> 5;
        int n   = nb * 32 + nq;
        float4 v = *(const float4*)(d_y + ((size_t)b * N_ + n0 + n) * O_ + ov);
        ys[(ov + 0) * 132 + n] = v.x;
        ys[(ov + 1) * 132 + n] = v.y;
        ys[(ov + 2) * 132 + n] = v.z;
        ys[(ov + 3) * 132 + n] = v.w;
    }
    __syncthreads();

    float acc[8][8];
#pragma unroll
    for (int i = 0; i < 8; i++)
#pragma unroll
        for (int j = 0; j < 8; j++) acc[i][j] = 0.f;

#pragma unroll 4
    for (int o = 0; o < 128; o++) {
        float a[8];
#pragma unroll
        for (int i = 0; i < 8; i++) a[i] = ws2[o * 132 + ty * 8 + i];
        float4 u = *(const float4*)&ys[o * 132 + tx * 8];
        float4 v = *(const float4*)&ys[o * 132 + tx * 8 + 4];
        float bb[8] = {u.x, u.y, u.z, u.w, v.x, v.y, v.z, v.w};
#pragma unroll
        for (int i = 0; i < 8; i++)
#pragma unroll
            for (int j = 0; j < 8; j++) acc[i][j] += a[i] * bb[j];
    }

    // Epilogue: BN (eval) + residual
#pragma unroll
    for (int i = 0; i < 8; i++) {
        int c = c0 + ty * 8 + i;
        float inv = gamma[c] * rsqrtf(var[c] + 1e-5f);
        float sh  = beta[c] - mean[c] * inv + bo[c] * inv;
        const float* xr = x   + ((size_t)(b * C_ + c)) * N_ + n0 + tx * 8;
        float*       orow = out + ((size_t)(b * C_ + c)) * N_ + n0 + tx * 8;
        float4 x0 = *(const float4*)xr;
        float4 x1 = *(const float4*)(xr + 4);
        float4 o0 = make_float4(x0.x + acc[i][0] * inv + sh,
                                x0.y + acc[i][1] * inv + sh,
                                x0.z + acc[i][2] * inv + sh,
                                x0.w + acc[i][3] * inv + sh);
        float4 o1 = make_float4(x1.x + acc[i][4] * inv + sh,
                                x1.y + acc[i][5] * inv + sh,
                                x1.z + acc[i][6] * inv + sh,
                                x1.w + acc[i][7] * inv + sh);
        *(float4*)orow       = o0;
        *(float4*)(orow + 4) = o1;
    }
}

// ---------------------------------------------------------------------------
extern "C" void kernel_launch(void* const* d_in, const int* in_sizes, int n_in,
                              void* d_out, int out_size)
{
    const float* x     = (const float*)d_in[0];
    const float* wt    = (const float*)d_in[1];
    const float* bt    = (const float*)d_in[2];
    const float* wp    = (const float*)d_in[3];
    const float* bp    = (const float*)d_in[4];
    const float* wg    = (const float*)d_in[5];
    const float* bg    = (const float*)d_in[6];
    const float* wo    = (const float*)d_in[7];
    const float* bo    = (const float*)d_in[8];
    const float* gamma = (const float*)d_in[9];
    const float* beta  = (const float*)d_in[10];
    const float* mean  = (const float*)d_in[11];
    const float* var   = (const float*)d_in[12];
    float* out = (float*)d_out;

    cudaFuncSetAttribute(attn_kernel, cudaFuncAttributeMaxDynamicSharedMemorySize, ATTN_SMEM);
    cudaFuncSetAttribute(out_kernel,  cudaFuncAttributeMaxDynamicSharedMemorySize, OUT_SMEM);

    proj_kernel<<<dim3(32, 8, 3), 256>>>(x, wt, bt, wp, bp, wg, bg);
    attn_kernel<<<dim3(32, 8), 256, ATTN_SMEM>>>();
    out_kernel<<<dim3(32, 2, 8), 256, OUT_SMEM>>>(x, wo, bo, gamma, beta, mean, var, out);
}

// round 5
// speedup vs baseline: 2.8596x; 2.8596x over previous
#include <cuda_runtime.h>
#include <cuda_bf16.h>
#include <cstdint>
#include <math.h>

#define B_ 8
#define C_ 256
#define N_ 4096
#define O_ 128
#define BK 64
#define NT (N_ / BK)

// Scratch (__device__ globals: allocation-free rule).
__device__ __nv_bfloat16 d_th_hi[(size_t)B_ * N_ * O_];
__device__ __nv_bfloat16 d_th_lo[(size_t)B_ * N_ * O_];
__device__ __nv_bfloat16 d_ph_hi[(size_t)B_ * N_ * O_];
__device__ __nv_bfloat16 d_ph_lo[(size_t)B_ * N_ * O_];
__device__ __nv_bfloat16 d_g   [(size_t)B_ * N_ * O_];
__device__ float         d_y   [(size_t)B_ * N_ * O_];

__device__ __forceinline__ uint32_t smem_u32(const void* p) {
    uint32_t a;
    asm("{ .reg .u64 t; cvta.to.shared.u64 t, %1; cvt.u32.u64 %0, t; }" : "=r"(a) : "l"(p));
    return a;
}

#define MMA16816(c, a, b0v, b1v) asm volatile( \
    "mma.sync.aligned.m16n8k16.row.col.f32.bf16.bf16.f32 " \
    "{%0,%1,%2,%3}, {%4,%5,%6,%7}, {%8,%9}, {%0,%1,%2,%3};" \
    : "+f"((c)[0]), "+f"((c)[1]), "+f"((c)[2]), "+f"((c)[3]) \
    : "r"((a)[0]), "r"((a)[1]), "r"((a)[2]), "r"((a)[3]), "r"(b0v), "r"(b1v))

#define LDSM2(r0, r1, addr)  asm volatile("ldmatrix.sync.aligned.m8n8.x2.shared.b16 {%0,%1}, [%2];" : "=r"(r0), "=r"(r1) : "r"(addr))
#define LDSM2T(r0, r1, addr) asm volatile("ldmatrix.sync.aligned.m8n8.x2.trans.shared.b16 {%0,%1}, [%2];" : "=r"(r0), "=r"(r1) : "r"(addr))
#define CP16(dst, src)   asm volatile("cp.async.cg.shared.global [%0], [%1], 16;" :: "r"(dst), "l"(src))
#define CP_COMMIT()      asm volatile("cp.async.commit_group;" ::: "memory")
#define CP_WAIT0()       asm volatile("cp.async.wait_group 0;" ::: "memory")
#define CP_WAIT1()       asm volatile("cp.async.wait_group 1;" ::: "memory")

__device__ __forceinline__ uint32_t bf16pair(float lo, float hi) {
    uint32_t r;   // PTX: cvt d, a, b -> d.hi = a, d.lo = b
    asm("cvt.rn.bf16x2.f32 %0, %1, %2;" : "=r"(r) : "f"(hi), "f"(lo));
    return r;
}

// smem layout (bytes): KH 2x17408 | KL 2x17408 | VH 2x17408. Pitch 272B/row.
#define KH_OFF 0
#define KL_OFF 34816
#define VH_OFF 69632
#define BUFSZ  17408
#define PITCH  272
#define ATTN_SMEM 104448

// ---------------------------------------------------------------------------
// Kernel 1: projections. theta/phi -> bf16 hi/lo [n][o]; g -> bf16 [n][o].
// ---------------------------------------------------------------------------
__global__ __launch_bounds__(256) void proj_kernel(
    const float* __restrict__ x,
    const float* __restrict__ wt, const float* __restrict__ bt,
    const float* __restrict__ wp, const float* __restrict__ bp,
    const float* __restrict__ wg, const float* __restrict__ bg)
{
    __shared__ float xs[32][132];
    __shared__ float ws[32][132];

    const int b  = blockIdx.y;
    const int n0 = blockIdx.x * 128;
    const int z  = blockIdx.z;
    const float* W; const float* bias;
    if (z == 0)      { W = wt; bias = bt; }
    else if (z == 1) { W = wp; bias = bp; }
    else             { W = wg; bias = bg; }

    const int tid = threadIdx.x;
    const int tx = tid & 15, ty = tid >> 4;

    float acc[8][8];
#pragma unroll
    for (int i = 0; i < 8; i++)
#pragma unroll
        for (int j = 0; j < 8; j++) acc[i][j] = 0.f;

    for (int c0 = 0; c0 < C_; c0 += 32) {
        __syncthreads();
#pragma unroll
        for (int r = 0; r < 4; r++) {
            int idx = tid + r * 256;
            int cc = idx >> 5, nv = (idx & 31) << 2;
            float4 v = *(const float4*)(x + ((size_t)(b * C_ + c0 + cc)) * N_ + n0 + nv);
            *(float4*)&xs[cc][nv] = v;
        }
#pragma unroll
        for (int r = 0; r < 4; r++) {
            int idx = tid + r * 256;
            int o = idx >> 3, cv = (idx & 7) << 2;
            float4 w = *(const float4*)(W + (size_t)o * C_ + c0 + cv);
            ws[cv + 0][o] = w.x; ws[cv + 1][o] = w.y;
            ws[cv + 2][o] = w.z; ws[cv + 3][o] = w.w;
        }
        __syncthreads();
#pragma unroll
        for (int cc = 0; cc < 32; cc++) {
            float a[8];
#pragma unroll
            for (int i = 0; i < 8; i++) a[i] = xs[cc][ty * 8 + i];
            float4 u = *(const float4*)&ws[cc][tx * 8];
            float4 v = *(const float4*)&ws[cc][tx * 8 + 4];
            float bb[8] = {u.x, u.y, u.z, u.w, v.x, v.y, v.z, v.w};
#pragma unroll
            for (int i = 0; i < 8; i++)
#pragma unroll
                for (int j = 0; j < 8; j++) acc[i][j] += a[i] * bb[j];
        }
    }

    float4 bu = *(const float4*)(bias + tx * 8);
    float4 bv = *(const float4*)(bias + tx * 8 + 4);
    float bb[8] = {bu.x, bu.y, bu.z, bu.w, bv.x, bv.y, bv.z, bv.w};

    if (z == 2) {
        __nv_bfloat16* og = d_g + (size_t)b * N_ * O_;
#pragma unroll
        for (int i = 0; i < 8; i++) {
            unsigned short hv[8];
#pragma unroll
            for (int j = 0; j < 8; j++)
                hv[j] = __bfloat16_as_ushort(__float2bfloat16(acc[i][j] + bb[j]));
            *(uint4*)(og + (size_t)(n0 + ty * 8 + i) * O_ + tx * 8) = *(uint4*)hv;
        }
    } else {
        __nv_bfloat16* ohi = (z == 0 ? d_th_hi : d_ph_hi) + (size_t)b * N_ * O_;
        __nv_bfloat16* olo = (z == 0 ? d_th_lo : d_ph_lo) + (size_t)b * N_ * O_;
#pragma unroll
        for (int i = 0; i < 8; i++) {
            unsigned short hi[8], lo[8];
#pragma unroll
            for (int j = 0; j < 8; j++) {
                float v = acc[i][j] + bb[j];
                __nv_bfloat16 h = __float2bfloat16(v);
                hi[j] = __bfloat16_as_ushort(h);
                lo[j] = __bfloat16_as_ushort(__float2bfloat16(v - __bfloat162float(h)));
            }
            size_t off = (size_t)(n0 + ty * 8 + i) * O_ + tx * 8;
            *(uint4*)(ohi + off) = *(uint4*)hi;
            *(uint4*)(olo + off) = *(uint4*)lo;
        }
    }
}

// ---------------------------------------------------------------------------
// Kernel 2: mma.sync flash attention (no-max softmax).
// grid (32 q-tiles, 8 b), 256 threads = 8 warps x 16 q-rows.
// ---------------------------------------------------------------------------
__global__ __launch_bounds__(256, 1) void attn_mma_kernel()
{
    extern __shared__ __align__(128) char smem[];
    const uint32_t sb = smem_u32(smem);
    const int tid = threadIdx.x;
    const int wid = tid >> 5, lane = tid & 31;
    const int b = blockIdx.y, q0 = blockIdx.x * 128;

    // ---- Q fragments (held in registers for the whole kernel) ----
    uint32_t qh[8][4], ql[8][4];
    {
        const __nv_bfloat16* Th = d_th_hi + ((size_t)b * N_ + q0 + wid * 16 + (lane >> 2)) * O_;
        const __nv_bfloat16* Tl = d_th_lo + ((size_t)b * N_ + q0 + wid * 16 + (lane >> 2)) * O_;
        const int c0 = 2 * (lane & 3);
#pragma unroll
        for (int s = 0; s < 8; s++) {
            qh[s][0] = *(const uint32_t*)(Th + s * 16 + c0);
            qh[s][1] = *(const uint32_t*)(Th + 8 * O_ + s * 16 + c0);
            qh[s][2] = *(const uint32_t*)(Th + s * 16 + c0 + 8);
            qh[s][3] = *(const uint32_t*)(Th + 8 * O_ + s * 16 + c0 + 8);
            ql[s][0] = *(const uint32_t*)(Tl + s * 16 + c0);
            ql[s][1] = *(const uint32_t*)(Tl + 8 * O_ + s * 16 + c0);
            ql[s][2] = *(const uint32_t*)(Tl + s * 16 + c0 + 8);
            ql[s][3] = *(const uint32_t*)(Tl + 8 * O_ + s * 16 + c0 + 8);
        }
    }

    const __nv_bfloat16* Ph = d_ph_hi + (size_t)b * N_ * O_;
    const __nv_bfloat16* Pl = d_ph_lo + (size_t)b * N_ * O_;
    const __nv_bfloat16* Vg = d_g    + (size_t)b * N_ * O_;

    // ldmatrix per-lane base addresses
    const uint32_t kbase = sb + KH_OFF + (lane & 7) * PITCH + ((lane >> 3) & 1) * 16;
    const uint32_t lbase = kbase + (KL_OFF - KH_OFF);
    const uint32_t vbase = sb + VH_OFF + (lane & 7) * PITCH + ((lane >> 3) & 1) * (8 * PITCH);

    float acc[16][4];
#pragma unroll
    for (int t = 0; t < 16; t++)
#pragma unroll
        for (int i = 0; i < 4; i++) acc[t][i] = 0.f;
    float l0 = 0.f, l1 = 0.f;

    // tile loader: 12 cp.async per thread (KH, KL, VH; 64 rows x 256B each)
    auto load_tile = [&](int jt, int buf) {
        const size_t k0 = (size_t)jt * BK;
        const uint32_t dst = sb + buf * BUFSZ;
#pragma unroll
        for (int r = 0; r < 4; r++) {
            int idx = tid + r * 256;
            int k = idx >> 4, ch = idx & 15;
            uint32_t off = (uint32_t)k * PITCH + ch * 16;
            const size_t g = (k0 + k) * O_ + ch * 8;
            CP16(dst + KH_OFF + off, Ph + g);
            CP16(dst + KL_OFF + off, Pl + g);
            CP16(dst + VH_OFF + off, Vg + g);
        }
    };

    load_tile(0, 0);
    CP_COMMIT();

    for (int j = 0; j < NT; j++) {
        const int buf = j & 1;
        if (j + 1 < NT) { load_tile(j + 1, buf ^ 1); CP_COMMIT(); CP_WAIT1(); }
        else           { CP_WAIT0(); }
        __syncthreads();

        // ---- S = Qh*Kh + Ql*Kh + Qh*Kl  (16 q x 64 keys per warp) ----
        float S[8][4];
#pragma unroll
        for (int jb = 0; jb < 8; jb++)
#pragma unroll
            for (int i = 0; i < 4; i++) S[jb][i] = 0.f;

        const uint32_t kb = kbase + buf * BUFSZ;
        const uint32_t lb = lbase + buf * BUFSZ;
#pragma unroll
        for (int s = 0; s < 8; s++) {
#pragma unroll
            for (int jb = 0; jb < 8; jb++) {
                uint32_t kh0, kh1, kl0, kl1;
                LDSM2(kh0, kh1, kb + jb * (8 * PITCH) + s * 32);
                LDSM2(kl0, kl1, lb + jb * (8 * PITCH) + s * 32);
                MMA16816(S[jb], qh[s], kh0, kh1);
                MMA16816(S[jb], ql[s], kh0, kh1);
                MMA16816(S[jb], qh[s], kl0, kl1);
            }
        }

        // ---- softmax (no max) + pack P into hi/lo A-fragments ----
        uint32_t ah[4][4], al[4][4];
#pragma unroll
        for (int jb = 0; jb < 8; jb++) {
            float p0 = __expf(S[jb][0]);
            float p1 = __expf(S[jb][1]);
            float p2 = __expf(S[jb][2]);
            float p3 = __expf(S[jb][3]);
            l0 += p0 + p1;
            l1 += p2 + p3;
            float h0 = __bfloat162float(__float2bfloat16(p0));
            float h1 = __bfloat162float(__float2bfloat16(p1));
            float h2 = __bfloat162float(__float2bfloat16(p2));
            float h3 = __bfloat162float(__float2bfloat16(p3));
            const int s2 = jb >> 1, hf = (jb & 1) * 2;
            ah[s2][hf + 0] = bf16pair(h0, h1);
            ah[s2][hf + 1] = bf16pair(h2, h3);
            al[s2][hf + 0] = bf16pair(p0 - h0, p1 - h1);
            al[s2][hf + 1] = bf16pair(p2 - h2, p3 - h3);
        }

        // ---- acc += (Ph + Pl) @ V ----
        const uint32_t vb = vbase + buf * BUFSZ;
#pragma unroll
        for (int s2 = 0; s2 < 4; s2++) {
#pragma unroll
            for (int t = 0; t < 16; t++) {
                uint32_t v0, v1;
                LDSM2T(v0, v1, vb + s2 * (16 * PITCH) + t * 16);
                MMA16816(acc[t], ah[s2], v0, v1);
                MMA16816(acc[t], al[s2], v0, v1);
            }
        }
        __syncthreads();   // everyone done with buf before it is overwritten
    }

    // ---- epilogue: row sums, divide, store y ----
    l0 += __shfl_xor_sync(0xffffffffu, l0, 1);
    l0 += __shfl_xor_sync(0xffffffffu, l0, 2);
    l1 += __shfl_xor_sync(0xffffffffu, l1, 1);
    l1 += __shfl_xor_sync(0xffffffffu, l1, 2);
    const float inv0 = 1.f / l0, inv1 = 1.f / l1;

    const int r0 = q0 + wid * 16 + (lane >> 2);
    float* y0 = d_y + ((size_t)b * N_ + r0) * O_ + 2 * (lane & 3);
    float* y1 = y0 + 8 * O_;
#pragma unroll
    for (int t = 0; t < 16; t++) {
        *(float2*)(y0 + t * 8) = make_float2(acc[t][0] * inv0, acc[t][1] * inv0);
        *(float2*)(y1 + t * 8) = make_float2(acc[t][2] * inv1, acc[t][3] * inv1);
    }
}

// ---------------------------------------------------------------------------
// Kernel 3: out = x + BN(W_out y + b_out).
// ---------------------------------------------------------------------------
#define OUT_SMEM (2 * 128 * 132 * 4)

__global__ __launch_bounds__(256, 1) void out_kernel(
    const float* __restrict__ x,
    const float* __restrict__ wo, const float* __restrict__ bo,
    const float* __restrict__ gamma, const float* __restrict__ beta,
    const float* __restrict__ mean, const float* __restrict__ var,
    float* __restrict__ out)
{
    extern __shared__ float sm[];
    float* ws2 = sm;
    float* ys  = sm + 128 * 132;

    const int b  = blockIdx.z;
    const int c0 = blockIdx.y * 128;
    const int n0 = blockIdx.x * 128;
    const int tid = threadIdx.x;
    const int tx = tid & 15, ty = tid >> 4;

#pragma unroll
    for (int r = 0; r < 16; r++) {
        int idx = tid + r * 256;
        int cq = idx & 31, grp = idx >> 5;
        int ov = (grp & 31) << 2, cb = grp >> 5;
        int c = cb * 32 + cq;
        float4 v = *(const float4*)(wo + (size_t)(c0 + c) * O_ + ov);
        ws2[(ov + 0) * 132 + c] = v.x; ws2[(ov + 1) * 132 + c] = v.y;
        ws2[(ov + 2) * 132 + c] = v.z; ws2[(ov + 3) * 132 + c] = v.w;
    }
#pragma unroll
    for (int r = 0; r < 16; r++) {
        int idx = tid + r * 256;
        int nq = idx & 31, grp = idx >> 5;
        int ov = (grp & 31) << 2, nb = grp >> 5;
        int n = nb * 32 + nq;
        float4 v = *(const float4*)(d_y + ((size_t)b * N_ + n0 + n) * O_ + ov);
        ys[(ov + 0) * 132 + n] = v.x; ys[(ov + 1) * 132 + n] = v.y;
        ys[(ov + 2) * 132 + n] = v.z; ys[(ov + 3) * 132 + n] = v.w;
    }
    __syncthreads();

    float acc[8][8];
#pragma unroll
    for (int i = 0; i < 8; i++)
#pragma unroll
        for (int j = 0; j < 8; j++) acc[i][j] = 0.f;

#pragma unroll 4
    for (int o = 0; o < 128; o++) {
        float a[8];
#pragma unroll
        for (int i = 0; i < 8; i++) a[i] = ws2[o * 132 + ty * 8 + i];
        float4 u = *(const float4*)&ys[o * 132 + tx * 8];
        float4 v = *(const float4*)&ys[o * 132 + tx * 8 + 4];
        float bb[8] = {u.x, u.y, u.z, u.w, v.x, v.y, v.z, v.w};
#pragma unroll
        for (int i = 0; i < 8; i++)
#pragma unroll
            for (int j = 0; j < 8; j++) acc[i][j] += a[i] * bb[j];
    }

#pragma unroll
    for (int i = 0; i < 8; i++) {
        int c = c0 + ty * 8 + i;
        float inv = gamma[c] * rsqrtf(var[c] + 1e-5f);
        float sh  = beta[c] - mean[c] * inv + bo[c] * inv;
        const float* xr = x + ((size_t)(b * C_ + c)) * N_ + n0 + tx * 8;
        float* orow = out + ((size_t)(b * C_ + c)) * N_ + n0 + tx * 8;
        float4 x0 = *(const float4*)xr;
        float4 x1 = *(const float4*)(xr + 4);
        *(float4*)orow = make_float4(
            x0.x + acc[i][0] * inv + sh, x0.y + acc[i][1] * inv + sh,
            x0.z + acc[i][2] * inv + sh, x0.w + acc[i][3] * inv + sh);
        *(float4*)(orow + 4) = make_float4(
            x1.x + acc[i][4] * inv + sh, x1.y + acc[i][5] * inv + sh,
            x1.z + acc[i][6] * inv + sh, x1.w + acc[i][7] * inv + sh);
    }
}

// ---------------------------------------------------------------------------
extern "C" void kernel_launch(void* const* d_in, const int* in_sizes, int n_in,
                              void* d_out, int out_size)
{
    const float* x     = (const float*)d_in[0];
    const float* wt    = (const float*)d_in[1];
    const float* bt    = (const float*)d_in[2];
    const float* wp    = (const float*)d_in[3];
    const float* bp    = (const float*)d_in[4];
    const float* wg    = (const float*)d_in[5];
    const float* bg    = (const float*)d_in[6];
    const float* wo    = (const float*)d_in[7];
    const float* bo    = (const float*)d_in[8];
    const float* gamma = (const float*)d_in[9];
    const float* beta  = (const float*)d_in[10];
    const float* mean  = (const float*)d_in[11];
    const float* var   = (const float*)d_in[12];
    float* out = (float*)d_out;

    cudaFuncSetAttribute(attn_mma_kernel, cudaFuncAttributeMaxDynamicSharedMemorySize, ATTN_SMEM);
    cudaFuncSetAttribute(out_kernel,      cudaFuncAttributeMaxDynamicSharedMemorySize, OUT_SMEM);

    proj_kernel<<<dim3(32, 8, 3), 256>>>(x, wt, bt, wp, bp, wg, bg);
    attn_mma_kernel<<<dim3(32, 8), 256, ATTN_SMEM>>>();
    out_kernel<<<dim3(32, 2, 8), 256, OUT_SMEM>>>(x, wo, bo, gamma, beta, mean, var, out);
}

// round 7
// speedup vs baseline: 4.4146x; 1.5437x over previous
#include <cuda_runtime.h>
#include <cuda_fp16.h>
#include <cstdint>
#include <math.h>

#define B_ 8
#define C_ 256
#define N_ 4096
#define O_ 128
#define BK 64
#define NT (N_ / BK)

// Scratch (__device__ globals: allocation-free rule). All fp16, 6 x 8MB.
__device__ __half d_th_hi[(size_t)B_ * N_ * O_];
__device__ __half d_th_lo[(size_t)B_ * N_ * O_];
__device__ __half d_ph_hi[(size_t)B_ * N_ * O_];
__device__ __half d_g    [(size_t)B_ * N_ * O_];
__device__ __half d_y_hi [(size_t)B_ * N_ * O_];
__device__ __half d_y_lo [(size_t)B_ * N_ * O_];

__device__ __forceinline__ uint32_t smem_u32(const void* p) {
    uint32_t a;
    asm("{ .reg .u64 t; cvta.to.shared.u64 t, %1; cvt.u32.u64 %0, t; }" : "=r"(a) : "l"(p));
    return a;
}

#define MMAF16(c, a, b0v, b1v) asm volatile( \
    "mma.sync.aligned.m16n8k16.row.col.f32.f16.f16.f32 " \
    "{%0,%1,%2,%3}, {%4,%5,%6,%7}, {%8,%9}, {%0,%1,%2,%3};" \
    : "+f"((c)[0]), "+f"((c)[1]), "+f"((c)[2]), "+f"((c)[3]) \
    : "r"((a)[0]), "r"((a)[1]), "r"((a)[2]), "r"((a)[3]), "r"(b0v), "r"(b1v))

#define LDSM2(r0, r1, addr)  asm volatile("ldmatrix.sync.aligned.m8n8.x2.shared.b16 {%0,%1}, [%2];" : "=r"(r0), "=r"(r1) : "r"(addr))
#define LDSM2T(r0, r1, addr) asm volatile("ldmatrix.sync.aligned.m8n8.x2.trans.shared.b16 {%0,%1}, [%2];" : "=r"(r0), "=r"(r1) : "r"(addr))
#define LDSM4(r0, r1, r2, r3, addr)  asm volatile("ldmatrix.sync.aligned.m8n8.x4.shared.b16 {%0,%1,%2,%3}, [%4];" : "=r"(r0), "=r"(r1), "=r"(r2), "=r"(r3) : "r"(addr))
#define LDSM4T(r0, r1, r2, r3, addr) asm volatile("ldmatrix.sync.aligned.m8n8.x4.trans.shared.b16 {%0,%1,%2,%3}, [%4];" : "=r"(r0), "=r"(r1), "=r"(r2), "=r"(r3) : "r"(addr))
#define CP16(dst, src)   asm volatile("cp.async.cg.shared.global [%0], [%1], 16;" :: "r"(dst), "l"(src))
#define CP_COMMIT()      asm volatile("cp.async.commit_group;" ::: "memory")
#define CP_WAIT0()       asm volatile("cp.async.wait_group 0;" ::: "memory")
#define CP_WAIT1()       asm volatile("cp.async.wait_group 1;" ::: "memory")

// pack two fp32 -> fp16x2, element a in LOW half (memory-first), b in HIGH
__device__ __forceinline__ uint32_t h2pair(float a, float b) {
    uint32_t r;
    asm("cvt.rn.f16x2.f32 %0, %1, %2;" : "=r"(r) : "f"(b), "f"(a));
    return r;
}

#define PITCH 272

// ---------------------------------------------------------------------------
// Kernel 1: projections via mma.sync (fp16 hi/lo 3-term split).
// out[n][o] = sum_c W[o][c] x[c][n] + bias.  A = x^T (ldmatrix.trans), B = W.
// grid (32 n-tiles, 8 b, 3 z), 256 threads = 8 warps x 16 n-rows.
// z=0: theta -> hi+lo.  z=1: phi -> hi.  z=2: g -> fp16.
// ---------------------------------------------------------------------------
#define PJ_WH 0
#define PJ_WL 67584
#define PJ_X  135168
#define PJ_XBUF 17408
#define PJ_PW 528
#define PROJ_SMEM 169984

__global__ __launch_bounds__(256, 1) void proj_kernel(
    const float* __restrict__ x,
    const float* __restrict__ wt, const float* __restrict__ bt,
    const float* __restrict__ wp, const float* __restrict__ bp,
    const float* __restrict__ wg, const float* __restrict__ bg)
{
    extern __shared__ __align__(128) char smem[];
    const uint32_t sb = smem_u32(smem);
    const int tid = threadIdx.x;
    const int wid = tid >> 5, lane = tid & 31;
    const int b = blockIdx.y, n0 = blockIdx.x * 128, z = blockIdx.z;
    const float* W; const float* bias;
    if (z == 0)      { W = wt; bias = bt; }
    else if (z == 1) { W = wp; bias = bp; }
    else             { W = wg; bias = bg; }

    // W -> smem (hi/lo fp16, pitch 528). 32 float4 per thread.
#pragma unroll
    for (int r = 0; r < 32; r++) {
        int idx = tid + r * 256;
        int o = idx >> 6, cv = (idx & 63) << 2;
        float4 w = *(const float4*)(W + (size_t)o * C_ + cv);
        __half hx = __float2half_rn(w.x), hy = __float2half_rn(w.y);
        __half hz = __float2half_rn(w.z), hw = __float2half_rn(w.w);
        uint32_t a0 = h2pair(__half2float(hx), __half2float(hy));
        uint32_t a1 = h2pair(__half2float(hz), __half2float(hw));
        uint32_t l0 = h2pair(w.x - __half2float(hx), w.y - __half2float(hy));
        uint32_t l1 = h2pair(w.z - __half2float(hz), w.w - __half2float(hw));
        uint32_t off = (uint32_t)o * PJ_PW + cv * 2;
        *(uint32_t*)(smem + PJ_WH + off)     = a0;
        *(uint32_t*)(smem + PJ_WH + off + 4) = a1;
        *(uint32_t*)(smem + PJ_WL + off)     = l0;
        *(uint32_t*)(smem + PJ_WL + off + 4) = l1;
    }

    float4 xr[4];
    auto ldg_chunk = [&](int ck) {
#pragma unroll
        for (int r = 0; r < 4; r++) {
            int idx = tid + r * 256;
            int cc = idx >> 5, nv = (idx & 31) << 2;
            xr[r] = *(const float4*)(x + ((size_t)(b * C_ + ck * 32 + cc)) * N_ + n0 + nv);
        }
    };
    auto sts_chunk = [&](int buf) {
#pragma unroll
        for (int r = 0; r < 4; r++) {
            int idx = tid + r * 256;
            int cc = idx >> 5, nv = (idx & 31) << 2;
            float4 v = xr[r];
            __half hx = __float2half_rn(v.x), hy = __float2half_rn(v.y);
            __half hz = __float2half_rn(v.z), hw = __float2half_rn(v.w);
            uint32_t base = PJ_X + buf * PJ_XBUF + (uint32_t)cc * PITCH + nv * 2;
            *(uint32_t*)(smem + base)     = h2pair(__half2float(hx), __half2float(hy));
            *(uint32_t*)(smem + base + 4) = h2pair(__half2float(hz), __half2float(hw));
            *(uint32_t*)(smem + base + 8704)     = h2pair(v.x - __half2float(hx), v.y - __half2float(hy));
            *(uint32_t*)(smem + base + 8704 + 4) = h2pair(v.z - __half2float(hz), v.w - __half2float(hw));
        }
    };

    ldg_chunk(0);
    sts_chunk(0);
    __syncthreads();

    float acc[16][4];
#pragma unroll
    for (int t = 0; t < 16; t++)
#pragma unroll
        for (int i = 0; i < 4; i++) acc[t][i] = 0.f;

    // per-lane ldmatrix bases
    const uint32_t xa_off = (uint32_t)((lane & 7) + ((lane >> 4) << 3)) * PITCH
                          + (uint32_t)(wid * 16 + (((lane >> 3) & 1) << 3)) * 2;
    const uint32_t wb_off = (uint32_t)(lane & 7) * PJ_PW + ((lane >> 3) & 1) * 16;

    for (int ck = 0; ck < 8; ck++) {
        const int buf = ck & 1;
        if (ck < 7) ldg_chunk(ck + 1);
        const uint32_t xb = sb + PJ_X + buf * PJ_XBUF + xa_off;
#pragma unroll
        for (int s = 0; s < 2; s++) {
            uint32_t ah[4], al[4];
            LDSM4T(ah[0], ah[1], ah[2], ah[3], xb + s * (16 * PITCH));
            LDSM4T(al[0], al[1], al[2], al[3], xb + s * (16 * PITCH) + 8704);
            const uint32_t wcol = sb + wb_off + (uint32_t)(ck * 32 + s * 16) * 2;
#pragma unroll
            for (int jb = 0; jb < 16; jb++) {
                uint32_t bh0, bh1, bl0, bl1;
                LDSM2(bh0, bh1, wcol + PJ_WH + jb * (8 * PJ_PW));
                LDSM2(bl0, bl1, wcol + PJ_WL + jb * (8 * PJ_PW));
                MMAF16(acc[jb], ah, bh0, bh1);
                MMAF16(acc[jb], al, bh0, bh1);
                MMAF16(acc[jb], ah, bl0, bl1);
            }
        }
        __syncthreads();
        if (ck < 7) { sts_chunk(buf ^ 1); __syncthreads(); }
    }

    // epilogue
    const int nr0 = n0 + wid * 16 + (lane >> 2);
    const size_t row0 = (size_t)b * N_ + nr0;
#pragma unroll
    for (int jb = 0; jb < 16; jb++) {
        const int o = jb * 8 + 2 * (lane & 3);
        float2 b2 = *(const float2*)(bias + o);
        float v0 = acc[jb][0] + b2.x, v1 = acc[jb][1] + b2.y;
        float v2 = acc[jb][2] + b2.x, v3 = acc[jb][3] + b2.y;
        if (z == 0) {
            __half h0 = __float2half_rn(v0), h1 = __float2half_rn(v1);
            __half h2 = __float2half_rn(v2), h3 = __float2half_rn(v3);
            *(uint32_t*)(d_th_hi + row0 * O_ + o) = h2pair(__half2float(h0), __half2float(h1));
            *(uint32_t*)(d_th_hi + (row0 + 8) * O_ + o) = h2pair(__half2float(h2), __half2float(h3));
            *(uint32_t*)(d_th_lo + row0 * O_ + o) = h2pair(v0 - __half2float(h0), v1 - __half2float(h1));
            *(uint32_t*)(d_th_lo + (row0 + 8) * O_ + o) = h2pair(v2 - __half2float(h2), v3 - __half2float(h3));
        } else if (z == 1) {
            *(uint32_t*)(d_ph_hi + row0 * O_ + o) = h2pair(v0, v1);
            *(uint32_t*)(d_ph_hi + (row0 + 8) * O_ + o) = h2pair(v2, v3);
        } else {
            *(uint32_t*)(d_g + row0 * O_ + o) = h2pair(v0, v1);
            *(uint32_t*)(d_g + (row0 + 8) * O_ + o) = h2pair(v2, v3);
        }
    }
}

// ---------------------------------------------------------------------------
// Kernel 2: fp16 flash attention with running max.
// QK: Qh*Kh + Ql*Kh (2 GEMMs).  PV: 1 fp16 GEMM.
// grid (32 q-tiles, 8 b), 256 threads = 8 warps x 16 q-rows.
// ---------------------------------------------------------------------------
#define AK_OFF 0
#define AV_OFF 34816
#define ABUF   17408
#define ATTN_SMEM 69632

__global__ __launch_bounds__(256, 1) void attn_kernel()
{
    extern __shared__ __align__(128) char smem[];
    const uint32_t sb = smem_u32(smem);
    const int tid = threadIdx.x;
    const int wid = tid >> 5, lane = tid & 31;
    const int b = blockIdx.y, q0 = blockIdx.x * 128;

    // Q fragments in registers
    uint32_t qh[8][4], ql[8][4];
    {
        const __half* Th = d_th_hi + ((size_t)b * N_ + q0 + wid * 16 + (lane >> 2)) * O_;
        const __half* Tl = d_th_lo + ((size_t)b * N_ + q0 + wid * 16 + (lane >> 2)) * O_;
        const int c0 = 2 * (lane & 3);
#pragma unroll
        for (int s = 0; s < 8; s++) {
            qh[s][0] = *(const uint32_t*)(Th + s * 16 + c0);
            qh[s][1] = *(const uint32_t*)(Th + 8 * O_ + s * 16 + c0);
            qh[s][2] = *(const uint32_t*)(Th + s * 16 + c0 + 8);
            qh[s][3] = *(const uint32_t*)(Th + 8 * O_ + s * 16 + c0 + 8);
            ql[s][0] = *(const uint32_t*)(Tl + s * 16 + c0);
            ql[s][1] = *(const uint32_t*)(Tl + 8 * O_ + s * 16 + c0);
            ql[s][2] = *(const uint32_t*)(Tl + s * 16 + c0 + 8);
            ql[s][3] = *(const uint32_t*)(Tl + 8 * O_ + s * 16 + c0 + 8);
        }
    }

    const __half* Ph = d_ph_hi + (size_t)b * N_ * O_;
    const __half* Vh = d_g    + (size_t)b * N_ * O_;

    const uint32_t kbase = sb + AK_OFF + (lane & 7) * PITCH + ((lane >> 3) & 1) * 16;
    const uint32_t vbase = sb + AV_OFF + (lane & 7) * PITCH + ((lane >> 3) & 1) * (8 * PITCH);

    float acc[16][4];
#pragma unroll
    for (int t = 0; t < 16; t++)
#pragma unroll
        for (int i = 0; i < 4; i++) acc[t][i] = 0.f;
    float m0 = -1e30f, m1 = -1e30f, l0 = 0.f, l1 = 0.f;

    auto load_tile = [&](int jt, int buf) {
        const size_t k0 = (size_t)jt * BK;
#pragma unroll
        for (int r = 0; r < 4; r++) {
            int idx = tid + r * 256;
            int k = idx >> 4, ch = idx & 15;
            uint32_t off = buf * ABUF + (uint32_t)k * PITCH + ch * 16;
            const size_t g = (k0 + k) * O_ + ch * 8;
            CP16(sb + AK_OFF + off, Ph + g);
            CP16(sb + AV_OFF + off, Vh + g);
        }
    };

    load_tile(0, 0);
    CP_COMMIT();

    for (int j = 0; j < NT; j++) {
        const int buf = j & 1;
        if (j + 1 < NT) { load_tile(j + 1, buf ^ 1); CP_COMMIT(); CP_WAIT1(); }
        else           { CP_WAIT0(); }
        __syncthreads();

        // S = Qh*Kh + Ql*Kh
        float S[8][4];
#pragma unroll
        for (int jb = 0; jb < 8; jb++)
#pragma unroll
            for (int i = 0; i < 4; i++) S[jb][i] = 0.f;
        const uint32_t kb = kbase + buf * ABUF;
#pragma unroll
        for (int s = 0; s < 8; s++) {
#pragma unroll
            for (int jb = 0; jb < 8; jb++) {
                uint32_t k0r, k1r;
                LDSM2(k0r, k1r, kb + jb * (8 * PITCH) + s * 32);
                MMAF16(S[jb], qh[s], k0r, k1r);
                MMAF16(S[jb], ql[s], k0r, k1r);
            }
        }

        // running max
        float mt0 = S[0][0], mt1 = S[0][2];
#pragma unroll
        for (int jb = 0; jb < 8; jb++) {
            mt0 = fmaxf(mt0, fmaxf(S[jb][0], S[jb][1]));
            mt1 = fmaxf(mt1, fmaxf(S[jb][2], S[jb][3]));
        }
        mt0 = fmaxf(mt0, __shfl_xor_sync(0xffffffffu, mt0, 1));
        mt0 = fmaxf(mt0, __shfl_xor_sync(0xffffffffu, mt0, 2));
        mt1 = fmaxf(mt1, __shfl_xor_sync(0xffffffffu, mt1, 1));
        mt1 = fmaxf(mt1, __shfl_xor_sync(0xffffffffu, mt1, 2));
        if (mt0 > m0) {
            float sc = __expf(m0 - mt0);
            l0 *= sc;
#pragma unroll
            for (int t = 0; t < 16; t++) { acc[t][0] *= sc; acc[t][1] *= sc; }
            m0 = mt0;
        }
        if (mt1 > m1) {
            float sc = __expf(m1 - mt1);
            l1 *= sc;
#pragma unroll
            for (int t = 0; t < 16; t++) { acc[t][2] *= sc; acc[t][3] *= sc; }
            m1 = mt1;
        }

        // P = exp(S - m), pack fp16, sum rounded values
        uint32_t ah[4][4];
#pragma unroll
        for (int jb = 0; jb < 8; jb++) {
            float p0 = __expf(S[jb][0] - m0), p1 = __expf(S[jb][1] - m0);
            float p2 = __expf(S[jb][2] - m1), p3 = __expf(S[jb][3] - m1);
            uint32_t pk0 = h2pair(p0, p1), pk2 = h2pair(p2, p3);
            __half2 f0 = *(__half2*)&pk0, f2 = *(__half2*)&pk2;
            l0 += __low2float(f0) + __high2float(f0);
            l1 += __low2float(f2) + __high2float(f2);
            ah[jb >> 1][(jb & 1) * 2]     = pk0;
            ah[jb >> 1][(jb & 1) * 2 + 1] = pk2;
        }

        // acc += P @ V
        const uint32_t vb = vbase + buf * ABUF;
#pragma unroll
        for (int s2 = 0; s2 < 4; s2++) {
#pragma unroll
            for (int t = 0; t < 16; t++) {
                uint32_t v0, v1;
                LDSM2T(v0, v1, vb + s2 * (16 * PITCH) + t * 16);
                MMAF16(acc[t], ah[s2], v0, v1);
            }
        }
        __syncthreads();
    }

    // epilogue: reduce sums, divide, write y hi/lo fp16
    l0 += __shfl_xor_sync(0xffffffffu, l0, 1);
    l0 += __shfl_xor_sync(0xffffffffu, l0, 2);
    l1 += __shfl_xor_sync(0xffffffffu, l1, 1);
    l1 += __shfl_xor_sync(0xffffffffu, l1, 2);
    const float inv0 = 1.f / l0, inv1 = 1.f / l1;

    const size_t row0 = (size_t)b * N_ + q0 + wid * 16 + (lane >> 2);
#pragma unroll
    for (int t = 0; t < 16; t++) {
        const int o = t * 8 + 2 * (lane & 3);
        float v0 = acc[t][0] * inv0, v1 = acc[t][1] * inv0;
        float v2 = acc[t][2] * inv1, v3 = acc[t][3] * inv1;
        __half h0 = __float2half_rn(v0), h1 = __float2half_rn(v1);
        __half h2 = __float2half_rn(v2), h3 = __float2half_rn(v3);
        *(uint32_t*)(d_y_hi + row0 * O_ + o) = h2pair(__half2float(h0), __half2float(h1));
        *(uint32_t*)(d_y_hi + (row0 + 8) * O_ + o) = h2pair(__half2float(h2), __half2float(h3));
        *(uint32_t*)(d_y_lo + row0 * O_ + o) = h2pair(v0 - __half2float(h0), v1 - __half2float(h1));
        *(uint32_t*)(d_y_lo + (row0 + 8) * O_ + o) = h2pair(v2 - __half2float(h2), v3 - __half2float(h3));
    }
}

// ---------------------------------------------------------------------------
// Kernel 3: out = x + BN(W_out y + b_out) via mma.sync (fp16 3-term).
// out[c][n]: A = W_out[c][o] (k=o), B = y[n][o].  grid (32 n, 2 c, 8 b).
// ---------------------------------------------------------------------------
#define OK_WH 0
#define OK_WL 34816
#define OK_YH 69632
#define OK_YL 104448
#define OUT_SMEM 139264

__global__ __launch_bounds__(256, 1) void out_kernel(
    const float* __restrict__ x,
    const float* __restrict__ wo, const float* __restrict__ bo,
    const float* __restrict__ gamma, const float* __restrict__ beta,
    const float* __restrict__ mean, const float* __restrict__ var,
    float* __restrict__ out)
{
    extern __shared__ __align__(128) char smem[];
    const uint32_t sb = smem_u32(smem);
    const int tid = threadIdx.x;
    const int wid = tid >> 5, lane = tid & 31;
    const int b = blockIdx.z, c0 = blockIdx.y * 128, n0 = blockIdx.x * 128;

    // y hi/lo via cp.async (fp16 gmem): 128 rows x 8 chunks of 32B = 1024 idx
#pragma unroll
    for (int r = 0; r < 4; r++) {
        int idx = tid + r * 256;
        int row = idx >> 3, ch = idx & 7;
        const size_t g = ((size_t)b * N_ + n0 + row) * O_ + ch * 16;
        uint32_t off = (uint32_t)row * PITCH + ch * 32;
        CP16(sb + OK_YH + off,      d_y_hi + g);
        CP16(sb + OK_YH + off + 16, d_y_hi + g + 8);
        CP16(sb + OK_YL + off,      d_y_lo + g);
        CP16(sb + OK_YL + off + 16, d_y_lo + g + 8);
    }
    CP_COMMIT();

    // W_out tile: fp32 -> hi/lo fp16 smem
#pragma unroll
    for (int r = 0; r < 16; r++) {
        int idx = tid + r * 256;
        int c = idx >> 5, ov = (idx & 31) << 2;
        float4 w = *(const float4*)(wo + (size_t)(c0 + c) * O_ + ov);
        __half hx = __float2half_rn(w.x), hy = __float2half_rn(w.y);
        __half hz = __float2half_rn(w.z), hw = __float2half_rn(w.w);
        uint32_t off = (uint32_t)c * PITCH + ov * 2;
        *(uint32_t*)(smem + OK_WH + off)     = h2pair(__half2float(hx), __half2float(hy));
        *(uint32_t*)(smem + OK_WH + off + 4) = h2pair(__half2float(hz), __half2float(hw));
        *(uint32_t*)(smem + OK_WL + off)     = h2pair(w.x - __half2float(hx), w.y - __half2float(hy));
        *(uint32_t*)(smem + OK_WL + off + 4) = h2pair(w.z - __half2float(hz), w.w - __half2float(hw));
    }
    CP_WAIT0();
    __syncthreads();

    float acc[16][4];
#pragma unroll
    for (int t = 0; t < 16; t++)
#pragma unroll
        for (int i = 0; i < 4; i++) acc[t][i] = 0.f;

    const uint32_t wa = sb + (uint32_t)(wid * 16 + (lane & 15)) * PITCH + ((lane >> 4) & 1) * 16;
    const uint32_t yb = sb + (lane & 7) * PITCH + ((lane >> 3) & 1) * 16;

#pragma unroll
    for (int s = 0; s < 8; s++) {
        uint32_t ahf[4], alf[4];
        LDSM4(ahf[0], ahf[1], ahf[2], ahf[3], wa + OK_WH + s * 32);
        LDSM4(alf[0], alf[1], alf[2], alf[3], wa + OK_WL + s * 32);
#pragma unroll
        for (int jb = 0; jb < 16; jb++) {
            uint32_t yh0, yh1, yl0, yl1;
            LDSM2(yh0, yh1, yb + OK_YH + jb * (8 * PITCH) + s * 32);
            LDSM2(yl0, yl1, yb + OK_YL + jb * (8 * PITCH) + s * 32);
            MMAF16(acc[jb], ahf, yh0, yh1);
            MMAF16(acc[jb], alf, yh0, yh1);
            MMAF16(acc[jb], ahf, yl0, yl1);
        }
    }

    // epilogue: BN + residual
    const int cr0 = c0 + wid * 16 + (lane >> 2);
#pragma unroll
    for (int h = 0; h < 2; h++) {
        const int c = cr0 + h * 8;
        const float inv = gamma[c] * rsqrtf(var[c] + 1e-5f);
        const float sh = beta[c] - mean[c] * inv + bo[c] * inv;
        const size_t rb = ((size_t)(b * C_ + c)) * N_ + n0 + 2 * (lane & 3);
#pragma unroll
        for (int jb = 0; jb < 16; jb++) {
            float2 xv = *(const float2*)(x + rb + jb * 8);
            float2 ov;
            ov.x = xv.x + acc[jb][2 * h + 0] * inv + sh;
            ov.y = xv.y + acc[jb][2 * h + 1] * inv + sh;
            *(float2*)(out + rb + jb * 8) = ov;
        }
    }
}

// ---------------------------------------------------------------------------
extern "C" void kernel_launch(void* const* d_in, const int* in_sizes, int n_in,
                              void* d_out, int out_size)
{
    const float* x     = (const float*)d_in[0];
    const float* wt    = (const float*)d_in[1];
    const float* bt    = (const float*)d_in[2];
    const float* wp    = (const float*)d_in[3];
    const float* bp    = (const float*)d_in[4];
    const float* wg    = (const float*)d_in[5];
    const float* bg    = (const float*)d_in[6];
    const float* wo    = (const float*)d_in[7];
    const float* bo    = (const float*)d_in[8];
    const float* gamma = (const float*)d_in[9];
    const float* beta  = (const float*)d_in[10];
    const float* mean  = (const float*)d_in[11];
    const float* var   = (const float*)d_in[12];
    float* out = (float*)d_out;

    cudaFuncSetAttribute(proj_kernel, cudaFuncAttributeMaxDynamicSharedMemorySize, PROJ_SMEM);
    cudaFuncSetAttribute(attn_kernel, cudaFuncAttributeMaxDynamicSharedMemorySize, ATTN_SMEM);
    cudaFuncSetAttribute(out_kernel,  cudaFuncAttributeMaxDynamicSharedMemorySize, OUT_SMEM);

    proj_kernel<<<dim3(32, 8, 3), 256, PROJ_SMEM>>>(x, wt, bt, wp, bp, wg, bg);
    attn_kernel<<<dim3(32, 8), 256, ATTN_SMEM>>>();
    out_kernel<<<dim3(32, 2, 8), 256, OUT_SMEM>>>(x, wo, bo, gamma, beta, mean, var, out);
}

// round 8
// speedup vs baseline: 5.6406x; 1.2777x over previous
#include <cuda_runtime.h>
#include <cuda_fp16.h>
#include <cstdint>
#include <math.h>

#define B_ 8
#define C_ 256
#define N_ 4096
#define O_ 128
#define BK 64
#define NT (N_ / BK)

// Scratch (__device__ globals: allocation-free rule).
__device__ __half d_th [(size_t)B_ * N_ * O_];
__device__ __half d_tl [(size_t)B_ * N_ * O_];   // theta lo (kept for possible fallback; unused)
__device__ __half d_ph [(size_t)B_ * N_ * O_];
__device__ __half d_g  [(size_t)B_ * N_ * O_];
__device__ __half d_y16[(size_t)B_ * N_ * O_];
__device__ __half d_w16[3 * O_ * C_];            // fp16 W for the 3 projections

__device__ __forceinline__ uint32_t smem_u32(const void* p) {
    uint32_t a;
    asm("{ .reg .u64 t; cvta.to.shared.u64 t, %1; cvt.u32.u64 %0, t; }" : "=r"(a) : "l"(p));
    return a;
}

#define MMAF16(c, a, b0v, b1v) asm volatile( \
    "mma.sync.aligned.m16n8k16.row.col.f32.f16.f16.f32 " \
    "{%0,%1,%2,%3}, {%4,%5,%6,%7}, {%8,%9}, {%0,%1,%2,%3};" \
    : "+f"((c)[0]), "+f"((c)[1]), "+f"((c)[2]), "+f"((c)[3]) \
    : "r"((a)[0]), "r"((a)[1]), "r"((a)[2]), "r"((a)[3]), "r"(b0v), "r"(b1v))

#define LDSM4(r0, r1, r2, r3, addr)  asm volatile("ldmatrix.sync.aligned.m8n8.x4.shared.b16 {%0,%1,%2,%3}, [%4];" : "=r"(r0), "=r"(r1), "=r"(r2), "=r"(r3) : "r"(addr))
#define LDSM4T(r0, r1, r2, r3, addr) asm volatile("ldmatrix.sync.aligned.m8n8.x4.trans.shared.b16 {%0,%1,%2,%3}, [%4];" : "=r"(r0), "=r"(r1), "=r"(r2), "=r"(r3) : "r"(addr))
#define CP16(dst, src)   asm volatile("cp.async.cg.shared.global [%0], [%1], 16;" :: "r"(dst), "l"(src))
#define CP_COMMIT()      asm volatile("cp.async.commit_group;" ::: "memory")
#define CP_WAIT0()       asm volatile("cp.async.wait_group 0;" ::: "memory")
#define CP_WAIT1()       asm volatile("cp.async.wait_group 1;" ::: "memory")

// pack two fp32 -> fp16x2, a in LOW half, b in HIGH
__device__ __forceinline__ uint32_t h2pair(float a, float b) {
    uint32_t r;
    asm("cvt.rn.f16x2.f32 %0, %1, %2;" : "=r"(r) : "f"(b), "f"(a));
    return r;
}

#define PITCH 272

// ---------------------------------------------------------------------------
// Kernel 0: convert the three projection weights to fp16 once.
// ---------------------------------------------------------------------------
__global__ void setup_kernel(const float* __restrict__ wt,
                             const float* __restrict__ wp,
                             const float* __restrict__ wg)
{
    const int z = blockIdx.x;
    const float* W = (z == 0) ? wt : (z == 1) ? wp : wg;
    __half* out = d_w16 + (size_t)z * O_ * C_;
    for (int i = threadIdx.x; i < O_ * C_ / 4; i += blockDim.x) {
        float4 w = *(const float4*)(W + i * 4);
        uint32_t p0 = h2pair(w.x, w.y), p1 = h2pair(w.z, w.w);
        *(uint32_t*)(out + i * 4) = p0;
        *(uint32_t*)(out + i * 4 + 2) = p1;
    }
}

// ---------------------------------------------------------------------------
// Kernel 1: projections via mma.sync, 2-term (x hi/lo, W fp16).
// out[n][o] = sum_c W[o][c] x[c][n] + bias.  grid (32 n, 8 b, 3 z), 256 thr.
// ---------------------------------------------------------------------------
#define PJ_WH 0
#define PJ_X  67584
#define PJ_XBUF 17408
#define PJ_PW 528
#define PROJ_SMEM 102400

__global__ __launch_bounds__(256, 1) void proj_kernel(
    const float* __restrict__ x,
    const float* __restrict__ bt, const float* __restrict__ bp,
    const float* __restrict__ bg)
{
    extern __shared__ __align__(128) char smem[];
    const uint32_t sb = smem_u32(smem);
    const int tid = threadIdx.x;
    const int wid = tid >> 5, lane = tid & 31;
    const int b = blockIdx.y, n0 = blockIdx.x * 128, z = blockIdx.z;
    const float* bias = (z == 0) ? bt : (z == 1) ? bp : bg;
    __half* outp = (z == 0) ? d_th : (z == 1) ? d_ph : d_g;
    const __half* Wg = d_w16 + (size_t)z * O_ * C_;

    // W fp16 -> smem via cp.async: 128 rows x 32 chunks of 16B
#pragma unroll
    for (int r = 0; r < 16; r++) {
        int idx = tid + r * 256;
        int o = idx >> 5, ch = idx & 31;
        CP16(sb + PJ_WH + (uint32_t)o * PJ_PW + ch * 16, Wg + (size_t)o * C_ + ch * 8);
    }
    CP_COMMIT();

    float4 xr[4];
    auto ldg_chunk = [&](int ck) {
#pragma unroll
        for (int r = 0; r < 4; r++) {
            int idx = tid + r * 256;
            int cc = idx >> 5, nv = (idx & 31) << 2;
            xr[r] = *(const float4*)(x + ((size_t)(b * C_ + ck * 32 + cc)) * N_ + n0 + nv);
        }
    };
    auto sts_chunk = [&](int buf) {
#pragma unroll
        for (int r = 0; r < 4; r++) {
            int idx = tid + r * 256;
            int cc = idx >> 5, nv = (idx & 31) << 2;
            float4 v = xr[r];
            __half hx = __float2half_rn(v.x), hy = __float2half_rn(v.y);
            __half hz = __float2half_rn(v.z), hw = __float2half_rn(v.w);
            uint32_t base = PJ_X + buf * PJ_XBUF + (uint32_t)cc * PITCH + nv * 2;
            *(uint32_t*)(smem + base)     = h2pair(__half2float(hx), __half2float(hy));
            *(uint32_t*)(smem + base + 4) = h2pair(__half2float(hz), __half2float(hw));
            *(uint32_t*)(smem + base + 8704)     = h2pair(v.x - __half2float(hx), v.y - __half2float(hy));
            *(uint32_t*)(smem + base + 8704 + 4) = h2pair(v.z - __half2float(hz), v.w - __half2float(hw));
        }
    };

    ldg_chunk(0);
    CP_WAIT0();
    sts_chunk(0);
    __syncthreads();

    float acc[16][4];
#pragma unroll
    for (int t = 0; t < 16; t++)
#pragma unroll
        for (int i = 0; i < 4; i++) acc[t][i] = 0.f;

    const uint32_t xa_off = (uint32_t)((lane & 7) + ((lane >> 4) << 3)) * PITCH
                          + (uint32_t)(wid * 16 + (((lane >> 3) & 1) << 3)) * 2;
    const uint32_t wb4 = (uint32_t)(lane & 7) * PJ_PW + ((lane >> 3) & 1) * 16
                       + (uint32_t)(lane >> 4) * (8 * PJ_PW);

    for (int ck = 0; ck < 8; ck++) {
        const int buf = ck & 1;
        if (ck < 7) ldg_chunk(ck + 1);
        const uint32_t xb = sb + PJ_X + buf * PJ_XBUF + xa_off;
#pragma unroll
        for (int s = 0; s < 2; s++) {
            uint32_t ah[4], al[4];
            LDSM4T(ah[0], ah[1], ah[2], ah[3], xb + s * (16 * PITCH));
            LDSM4T(al[0], al[1], al[2], al[3], xb + s * (16 * PITCH) + 8704);
            const uint32_t wcol = sb + PJ_WH + wb4 + (uint32_t)(ck * 32 + s * 16) * 2;
#pragma unroll
            for (int jb2 = 0; jb2 < 8; jb2++) {
                uint32_t b0, b1, b2, b3;
                LDSM4(b0, b1, b2, b3, wcol + jb2 * (16 * PJ_PW));
                MMAF16(acc[2 * jb2],     ah, b0, b1);
                MMAF16(acc[2 * jb2],     al, b0, b1);
                MMAF16(acc[2 * jb2 + 1], ah, b2, b3);
                MMAF16(acc[2 * jb2 + 1], al, b2, b3);
            }
        }
        if (ck < 7) sts_chunk(buf ^ 1);
        __syncthreads();
    }

    const size_t row0 = (size_t)b * N_ + n0 + wid * 16 + (lane >> 2);
#pragma unroll
    for (int jb = 0; jb < 16; jb++) {
        const int o = jb * 8 + 2 * (lane & 3);
        float2 b2 = *(const float2*)(bias + o);
        *(uint32_t*)(outp + row0 * O_ + o)       = h2pair(acc[jb][0] + b2.x, acc[jb][1] + b2.y);
        *(uint32_t*)(outp + (row0 + 8) * O_ + o) = h2pair(acc[jb][2] + b2.x, acc[jb][3] + b2.y);
    }
}

// ---------------------------------------------------------------------------
// Kernel 2: fp16 flash attention. BM=64, 128 threads (4 warps), 2 CTAs/SM.
// QK: 1 fp16 GEMM.  PV: 1 fp16 GEMM.  grid (64 q-tiles, 8 b).
// ---------------------------------------------------------------------------
#define AK_OFF 0
#define AV_OFF 34816
#define ABUF   17408
#define ATTN_SMEM 69632

__global__ __launch_bounds__(128, 2) void attn_kernel()
{
    extern __shared__ __align__(128) char smem[];
    const uint32_t sb = smem_u32(smem);
    const int tid = threadIdx.x;
    const int wid = tid >> 5, lane = tid & 31;
    const int b = blockIdx.y, q0 = blockIdx.x * 64;

    // Q fragments in registers
    uint32_t qh[8][4];
    {
        const __half* Th = d_th + ((size_t)b * N_ + q0 + wid * 16 + (lane >> 2)) * O_;
        const int c0 = 2 * (lane & 3);
#pragma unroll
        for (int s = 0; s < 8; s++) {
            qh[s][0] = *(const uint32_t*)(Th + s * 16 + c0);
            qh[s][1] = *(const uint32_t*)(Th + 8 * O_ + s * 16 + c0);
            qh[s][2] = *(const uint32_t*)(Th + s * 16 + c0 + 8);
            qh[s][3] = *(const uint32_t*)(Th + 8 * O_ + s * 16 + c0 + 8);
        }
    }

    const __half* Ph = d_ph + (size_t)b * N_ * O_;
    const __half* Vh = d_g  + (size_t)b * N_ * O_;

    const uint32_t kb4 = sb + AK_OFF + (lane & 7) * PITCH + ((lane >> 3) & 1) * 16
                       + (lane >> 4) * (8 * PITCH);
    const uint32_t vb4 = sb + AV_OFF + (lane & 7) * PITCH + ((lane >> 3) & 1) * (8 * PITCH)
                       + (lane >> 4) * 16;

    float acc[16][4];
#pragma unroll
    for (int t = 0; t < 16; t++)
#pragma unroll
        for (int i = 0; i < 4; i++) acc[t][i] = 0.f;
    float m0 = -1e30f, m1 = -1e30f, l0 = 0.f, l1 = 0.f;

    auto load_tile = [&](int jt, int buf) {
        const size_t k0 = (size_t)jt * BK;
#pragma unroll
        for (int r = 0; r < 8; r++) {
            int idx = tid + r * 128;
            int k = idx >> 4, ch = idx & 15;
            uint32_t off = buf * ABUF + (uint32_t)k * PITCH + ch * 16;
            const size_t g = (k0 + k) * O_ + ch * 8;
            CP16(sb + AK_OFF + off, Ph + g);
            CP16(sb + AV_OFF + off, Vh + g);
        }
    };

    load_tile(0, 0);
    CP_COMMIT();

    for (int j = 0; j < NT; j++) {
        const int buf = j & 1;
        if (j + 1 < NT) { load_tile(j + 1, buf ^ 1); CP_COMMIT(); CP_WAIT1(); }
        else           { CP_WAIT0(); }
        __syncthreads();

        // S = Q K^T (single fp16 GEMM)
        float S[8][4];
#pragma unroll
        for (int jb = 0; jb < 8; jb++)
#pragma unroll
            for (int i = 0; i < 4; i++) S[jb][i] = 0.f;
        const uint32_t kb = kb4 + buf * ABUF;
#pragma unroll
        for (int s = 0; s < 8; s++) {
#pragma unroll
            for (int jb2 = 0; jb2 < 4; jb2++) {
                uint32_t b0, b1, b2, b3;
                LDSM4(b0, b1, b2, b3, kb + jb2 * (16 * PITCH) + s * 32);
                MMAF16(S[2 * jb2],     qh[s], b0, b1);
                MMAF16(S[2 * jb2 + 1], qh[s], b2, b3);
            }
        }

        // running max (branchless rescale)
        float mt0 = S[0][0], mt1 = S[0][2];
#pragma unroll
        for (int jb = 0; jb < 8; jb++) {
            mt0 = fmaxf(mt0, fmaxf(S[jb][0], S[jb][1]));
            mt1 = fmaxf(mt1, fmaxf(S[jb][2], S[jb][3]));
        }
        mt0 = fmaxf(mt0, __shfl_xor_sync(0xffffffffu, mt0, 1));
        mt0 = fmaxf(mt0, __shfl_xor_sync(0xffffffffu, mt0, 2));
        mt1 = fmaxf(mt1, __shfl_xor_sync(0xffffffffu, mt1, 1));
        mt1 = fmaxf(mt1, __shfl_xor_sync(0xffffffffu, mt1, 2));
        float m0n = fmaxf(m0, mt0), m1n = fmaxf(m1, mt1);
        float sc0 = __expf(m0 - m0n), sc1 = __expf(m1 - m1n);
        m0 = m0n; m1 = m1n;
        l0 *= sc0; l1 *= sc1;
#pragma unroll
        for (int t = 0; t < 16; t++) {
            acc[t][0] *= sc0; acc[t][1] *= sc0;
            acc[t][2] *= sc1; acc[t][3] *= sc1;
        }

        // P = exp(S - m) in fp16; sum the rounded values
        uint32_t ah[4][4];
#pragma unroll
        for (int jb = 0; jb < 8; jb++) {
            float p0 = __expf(S[jb][0] - m0), p1 = __expf(S[jb][1] - m0);
            float p2 = __expf(S[jb][2] - m1), p3 = __expf(S[jb][3] - m1);
            uint32_t pk0 = h2pair(p0, p1), pk2 = h2pair(p2, p3);
            __half2 f0 = *(__half2*)&pk0, f2 = *(__half2*)&pk2;
            l0 += __low2float(f0) + __high2float(f0);
            l1 += __low2float(f2) + __high2float(f2);
            ah[jb >> 1][(jb & 1) * 2]     = pk0;
            ah[jb >> 1][(jb & 1) * 2 + 1] = pk2;
        }

        // acc += P @ V
        const uint32_t vb = vb4 + buf * ABUF;
#pragma unroll
        for (int s2 = 0; s2 < 4; s2++) {
#pragma unroll
            for (int t2 = 0; t2 < 8; t2++) {
                uint32_t v0, v1, v2, v3;
                LDSM4T(v0, v1, v2, v3, vb + s2 * (16 * PITCH) + t2 * 32);
                MMAF16(acc[2 * t2],     ah[s2], v0, v1);
                MMAF16(acc[2 * t2 + 1], ah[s2], v2, v3);
            }
        }
        __syncthreads();
    }

    // epilogue
    l0 += __shfl_xor_sync(0xffffffffu, l0, 1);
    l0 += __shfl_xor_sync(0xffffffffu, l0, 2);
    l1 += __shfl_xor_sync(0xffffffffu, l1, 1);
    l1 += __shfl_xor_sync(0xffffffffu, l1, 2);
    const float inv0 = 1.f / l0, inv1 = 1.f / l1;

    const size_t row0 = (size_t)b * N_ + q0 + wid * 16 + (lane >> 2);
#pragma unroll
    for (int t = 0; t < 16; t++) {
        const int o = t * 8 + 2 * (lane & 3);
        *(uint32_t*)(d_y16 + row0 * O_ + o)       = h2pair(acc[t][0] * inv0, acc[t][1] * inv0);
        *(uint32_t*)(d_y16 + (row0 + 8) * O_ + o) = h2pair(acc[t][2] * inv1, acc[t][3] * inv1);
    }
}

// ---------------------------------------------------------------------------
// Kernel 3: out = x + BN(W_out y + b_out), single fp16 GEMM.
// grid (32 n, 2 c, 8 b), 256 threads.
// ---------------------------------------------------------------------------
#define OK_WH 0
#define OK_YH 34816
#define OUT_SMEM 69632

__global__ __launch_bounds__(256, 1) void out_kernel(
    const float* __restrict__ x,
    const float* __restrict__ wo, const float* __restrict__ bo,
    const float* __restrict__ gamma, const float* __restrict__ beta,
    const float* __restrict__ mean, const float* __restrict__ var,
    float* __restrict__ out)
{
    extern __shared__ __align__(128) char smem[];
    const uint32_t sb = smem_u32(smem);
    const int tid = threadIdx.x;
    const int wid = tid >> 5, lane = tid & 31;
    const int b = blockIdx.z, c0 = blockIdx.y * 128, n0 = blockIdx.x * 128;

    // y fp16 via cp.async: 128 rows x 8 chunks of 32B
#pragma unroll
    for (int r = 0; r < 4; r++) {
        int idx = tid + r * 256;
        int row = idx >> 3, ch = idx & 7;
        const size_t g = ((size_t)b * N_ + n0 + row) * O_ + ch * 16;
        uint32_t off = (uint32_t)row * PITCH + ch * 32;
        CP16(sb + OK_YH + off,      d_y16 + g);
        CP16(sb + OK_YH + off + 16, d_y16 + g + 8);
    }
    CP_COMMIT();

    // W_out tile fp32 -> fp16 smem
#pragma unroll
    for (int r = 0; r < 16; r++) {
        int idx = tid + r * 256;
        int c = idx >> 5, ov = (idx & 31) << 2;
        float4 w = *(const float4*)(wo + (size_t)(c0 + c) * O_ + ov);
        uint32_t off = (uint32_t)c * PITCH + ov * 2;
        *(uint32_t*)(smem + OK_WH + off)     = h2pair(w.x, w.y);
        *(uint32_t*)(smem + OK_WH + off + 4) = h2pair(w.z, w.w);
    }
    CP_WAIT0();
    __syncthreads();

    float acc[16][4];
#pragma unroll
    for (int t = 0; t < 16; t++)
#pragma unroll
        for (int i = 0; i < 4; i++) acc[t][i] = 0.f;

    const uint32_t wa  = sb + OK_WH + (uint32_t)(wid * 16 + (lane & 15)) * PITCH + ((lane >> 4) & 1) * 16;
    const uint32_t yb4 = sb + OK_YH + (lane & 7) * PITCH + ((lane >> 3) & 1) * 16
                       + (lane >> 4) * (8 * PITCH);

#pragma unroll
    for (int s = 0; s < 8; s++) {
        uint32_t ahf[4];
        LDSM4(ahf[0], ahf[1], ahf[2], ahf[3], wa + s * 32);
#pragma unroll
        for (int jb2 = 0; jb2 < 8; jb2++) {
            uint32_t y0, y1, y2, y3;
            LDSM4(y0, y1, y2, y3, yb4 + jb2 * (16 * PITCH) + s * 32);
            MMAF16(acc[2 * jb2],     ahf, y0, y1);
            MMAF16(acc[2 * jb2 + 1], ahf, y2, y3);
        }
    }

    // epilogue: BN + residual
    const int cr0 = c0 + wid * 16 + (lane >> 2);
#pragma unroll
    for (int h = 0; h < 2; h++) {
        const int c = cr0 + h * 8;
        const float inv = gamma[c] * rsqrtf(var[c] + 1e-5f);
        const float sh = beta[c] - mean[c] * inv + bo[c] * inv;
        const size_t rb = ((size_t)(b * C_ + c)) * N_ + n0 + 2 * (lane & 3);
#pragma unroll
        for (int jb = 0; jb < 16; jb++) {
            float2 xv = *(const float2*)(x + rb + jb * 8);
            float2 ov;
            ov.x = xv.x + acc[jb][2 * h + 0] * inv + sh;
            ov.y = xv.y + acc[jb][2 * h + 1] * inv + sh;
            *(float2*)(out + rb + jb * 8) = ov;
        }
    }
}

// ---------------------------------------------------------------------------
extern "C" void kernel_launch(void* const* d_in, const int* in_sizes, int n_in,
                              void* d_out, int out_size)
{
    const float* x     = (const float*)d_in[0];
    const float* wt    = (const float*)d_in[1];
    const float* bt    = (const float*)d_in[2];
    const float* wp    = (const float*)d_in[3];
    const float* bp    = (const float*)d_in[4];
    const float* wg    = (const float*)d_in[5];
    const float* bg    = (const float*)d_in[6];
    const float* wo    = (const float*)d_in[7];
    const float* bo    = (const float*)d_in[8];
    const float* gamma = (const float*)d_in[9];
    const float* beta  = (const float*)d_in[10];
    const float* mean  = (const float*)d_in[11];
    const float* var   = (const float*)d_in[12];
    float* out = (float*)d_out;

    cudaFuncSetAttribute(proj_kernel, cudaFuncAttributeMaxDynamicSharedMemorySize, PROJ_SMEM);
    cudaFuncSetAttribute(attn_kernel, cudaFuncAttributeMaxDynamicSharedMemorySize, ATTN_SMEM);
    cudaFuncSetAttribute(out_kernel,  cudaFuncAttributeMaxDynamicSharedMemorySize, OUT_SMEM);

    setup_kernel<<<3, 256>>>(wt, wp, wg);
    proj_kernel<<<dim3(32, 8, 3), 256, PROJ_SMEM>>>(x, bt, bp, bg);
    attn_kernel<<<dim3(64, 8), 128, ATTN_SMEM>>>();
    out_kernel<<<dim3(32, 2, 8), 256, OUT_SMEM>>>(x, wo, bo, gamma, beta, mean, var, out);
}

// round 9
// speedup vs baseline: 6.3674x; 1.1288x over previous
#include <cuda_runtime.h>
#include <cuda_fp16.h>
#include <cstdint>
#include <math.h>

#define B_ 8
#define C_ 256
#define N_ 4096
#define O_ 128
#define BK2 128
#define NT2 (N_ / BK2)

// Scratch (__device__ globals: allocation-free rule).
__device__ __half d_th [(size_t)B_ * N_ * O_];
__device__ __half d_ph [(size_t)B_ * N_ * O_];
__device__ __half d_g  [(size_t)B_ * N_ * O_];
__device__ __half d_y16[(size_t)B_ * N_ * O_];
__device__ __half d_w16[3 * O_ * C_];

__device__ __forceinline__ uint32_t smem_u32(const void* p) {
    uint32_t a;
    asm("{ .reg .u64 t; cvta.to.shared.u64 t, %1; cvt.u32.u64 %0, t; }" : "=r"(a) : "l"(p));
    return a;
}

#define MMAF16(c, a, b0v, b1v) asm volatile( \
    "mma.sync.aligned.m16n8k16.row.col.f32.f16.f16.f32 " \
    "{%0,%1,%2,%3}, {%4,%5,%6,%7}, {%8,%9}, {%0,%1,%2,%3};" \
    : "+f"((c)[0]), "+f"((c)[1]), "+f"((c)[2]), "+f"((c)[3]) \
    : "r"((a)[0]), "r"((a)[1]), "r"((a)[2]), "r"((a)[3]), "r"(b0v), "r"(b1v))

#define LDSM4(r0, r1, r2, r3, addr)  asm volatile("ldmatrix.sync.aligned.m8n8.x4.shared.b16 {%0,%1,%2,%3}, [%4];" : "=r"(r0), "=r"(r1), "=r"(r2), "=r"(r3) : "r"(addr))
#define LDSM4T(r0, r1, r2, r3, addr) asm volatile("ldmatrix.sync.aligned.m8n8.x4.trans.shared.b16 {%0,%1,%2,%3}, [%4];" : "=r"(r0), "=r"(r1), "=r"(r2), "=r"(r3) : "r"(addr))
#define CP16(dst, src)   asm volatile("cp.async.cg.shared.global [%0], [%1], 16;" :: "r"(dst), "l"(src))
#define CP_COMMIT()      asm volatile("cp.async.commit_group;" ::: "memory")
#define CP_WAIT0()       asm volatile("cp.async.wait_group 0;" ::: "memory")
#define CP_WAIT1()       asm volatile("cp.async.wait_group 1;" ::: "memory")

__device__ __forceinline__ uint32_t h2pair(float a, float b) {
    uint32_t r;
    asm("cvt.rn.f16x2.f32 %0, %1, %2;" : "=r"(r) : "f"(b), "f"(a));
    return r;
}

#define PITCH 272

// ---------------------------------------------------------------------------
// Kernel 0: W -> fp16 once.
// ---------------------------------------------------------------------------
__global__ void setup_kernel(const float* __restrict__ wt,
                             const float* __restrict__ wp,
                             const float* __restrict__ wg)
{
    const int z = blockIdx.x;
    const float* W = (z == 0) ? wt : (z == 1) ? wp : wg;
    __half* out = d_w16 + (size_t)z * O_ * C_;
    for (int i = threadIdx.x; i < O_ * C_ / 4; i += blockDim.x) {
        float4 w = *(const float4*)(W + i * 4);
        *(uint32_t*)(out + i * 4)     = h2pair(w.x, w.y);
        *(uint32_t*)(out + i * 4 + 2) = h2pair(w.z, w.w);
    }
}

// ---------------------------------------------------------------------------
// Kernel 1: projections, single-term fp16 (x fp16, W fp16).
// out[n][o] = sum_c W[o][c] x[c][n] + bias.  grid (32 n, 8 b, 3 z), 256 thr.
// ---------------------------------------------------------------------------
#define PJ_WH 0
#define PJ_X  67584
#define PJ_XBUF 8704
#define PJ_PW 528
#define PROJ_SMEM 84992

__global__ __launch_bounds__(256, 1) void proj_kernel(
    const float* __restrict__ x,
    const float* __restrict__ bt, const float* __restrict__ bp,
    const float* __restrict__ bg)
{
    extern __shared__ __align__(128) char smem[];
    const uint32_t sb = smem_u32(smem);
    const int tid = threadIdx.x;
    const int wid = tid >> 5, lane = tid & 31;
    const int b = blockIdx.y, n0 = blockIdx.x * 128, z = blockIdx.z;
    const float* bias = (z == 0) ? bt : (z == 1) ? bp : bg;
    __half* outp = (z == 0) ? d_th : (z == 1) ? d_ph : d_g;
    const __half* Wg = d_w16 + (size_t)z * O_ * C_;

    // W fp16 -> smem via cp.async: 128 rows x 32 chunks of 16B
#pragma unroll
    for (int r = 0; r < 16; r++) {
        int idx = tid + r * 256;
        int o = idx >> 5, ch = idx & 31;
        CP16(sb + PJ_WH + (uint32_t)o * PJ_PW + ch * 16, Wg + (size_t)o * C_ + ch * 8);
    }
    CP_COMMIT();

    float4 xr[4];
    auto ldg_chunk = [&](int ck) {
#pragma unroll
        for (int r = 0; r < 4; r++) {
            int idx = tid + r * 256;
            int cc = idx >> 5, nv = (idx & 31) << 2;
            xr[r] = *(const float4*)(x + ((size_t)(b * C_ + ck * 32 + cc)) * N_ + n0 + nv);
        }
    };
    auto sts_chunk = [&](int buf) {
#pragma unroll
        for (int r = 0; r < 4; r++) {
            int idx = tid + r * 256;
            int cc = idx >> 5, nv = (idx & 31) << 2;
            float4 v = xr[r];
            uint32_t base = PJ_X + buf * PJ_XBUF + (uint32_t)cc * PITCH + nv * 2;
            *(uint32_t*)(smem + base)     = h2pair(v.x, v.y);
            *(uint32_t*)(smem + base + 4) = h2pair(v.z, v.w);
        }
    };

    ldg_chunk(0);
    CP_WAIT0();
    sts_chunk(0);
    __syncthreads();

    float acc[16][4];
#pragma unroll
    for (int t = 0; t < 16; t++)
#pragma unroll
        for (int i = 0; i < 4; i++) acc[t][i] = 0.f;

    const uint32_t xa_off = (uint32_t)((lane & 7) + ((lane >> 4) << 3)) * PITCH
                          + (uint32_t)(wid * 16 + (((lane >> 3) & 1) << 3)) * 2;
    const uint32_t wb4 = (uint32_t)(lane & 7) * PJ_PW + ((lane >> 3) & 1) * 16
                       + (uint32_t)(lane >> 4) * (8 * PJ_PW);

    for (int ck = 0; ck < 8; ck++) {
        const int buf = ck & 1;
        if (ck < 7) ldg_chunk(ck + 1);
        const uint32_t xb = sb + PJ_X + buf * PJ_XBUF + xa_off;
#pragma unroll
        for (int s = 0; s < 2; s++) {
            uint32_t ah[4];
            LDSM4T(ah[0], ah[1], ah[2], ah[3], xb + s * (16 * PITCH));
            const uint32_t wcol = sb + PJ_WH + wb4 + (uint32_t)(ck * 32 + s * 16) * 2;
#pragma unroll
            for (int jb2 = 0; jb2 < 8; jb2++) {
                uint32_t b0, b1, b2, b3;
                LDSM4(b0, b1, b2, b3, wcol + jb2 * (16 * PJ_PW));
                MMAF16(acc[2 * jb2],     ah, b0, b1);
                MMAF16(acc[2 * jb2 + 1], ah, b2, b3);
            }
        }
        if (ck < 7) sts_chunk(buf ^ 1);
        __syncthreads();
    }

    const size_t row0 = (size_t)b * N_ + n0 + wid * 16 + (lane >> 2);
#pragma unroll
    for (int jb = 0; jb < 16; jb++) {
        const int o = jb * 8 + 2 * (lane & 3);
        float2 b2 = *(const float2*)(bias + o);
        *(uint32_t*)(outp + row0 * O_ + o)       = h2pair(acc[jb][0] + b2.x, acc[jb][1] + b2.y);
        *(uint32_t*)(outp + (row0 + 8) * O_ + o) = h2pair(acc[jb][2] + b2.x, acc[jb][3] + b2.y);
    }
}

// ---------------------------------------------------------------------------
// Kernel 2: fp16 flash attention. BM=128, BK=128, 256 threads (8 warps).
// grid (32 q-tiles, 8 b).  1 CTA/SM, 139KB smem.
// ---------------------------------------------------------------------------
#define AK_OFF 0
#define AV_OFF 34816
#define ABUF   69632
#define ATTN_SMEM 139264

__global__ __launch_bounds__(256, 1) void attn_kernel()
{
    extern __shared__ __align__(128) char smem[];
    const uint32_t sb = smem_u32(smem);
    const int tid = threadIdx.x;
    const int wid = tid >> 5, lane = tid & 31;
    const int b = blockIdx.y, q0 = blockIdx.x * 128;

    // Q fragments in registers (16 q-rows per warp, full d=128)
    uint32_t qh[8][4];
    {
        const __half* Th = d_th + ((size_t)b * N_ + q0 + wid * 16 + (lane >> 2)) * O_;
        const int c0 = 2 * (lane & 3);
#pragma unroll
        for (int s = 0; s < 8; s++) {
            qh[s][0] = *(const uint32_t*)(Th + s * 16 + c0);
            qh[s][1] = *(const uint32_t*)(Th + 8 * O_ + s * 16 + c0);
            qh[s][2] = *(const uint32_t*)(Th + s * 16 + c0 + 8);
            qh[s][3] = *(const uint32_t*)(Th + 8 * O_ + s * 16 + c0 + 8);
        }
    }

    const __half* Ph = d_ph + (size_t)b * N_ * O_;
    const __half* Vh = d_g  + (size_t)b * N_ * O_;

    const uint32_t kb4 = sb + AK_OFF + (lane & 7) * PITCH + ((lane >> 3) & 1) * 16
                       + (lane >> 4) * (8 * PITCH);
    const uint32_t vb4 = sb + AV_OFF + (lane & 7) * PITCH + ((lane >> 3) & 1) * (8 * PITCH)
                       + (lane >> 4) * 16;

    float acc[16][4];
#pragma unroll
    for (int t = 0; t < 16; t++)
#pragma unroll
        for (int i = 0; i < 4; i++) acc[t][i] = 0.f;
    float m0 = -1e30f, m1 = -1e30f, l0 = 0.f, l1 = 0.f;

    // tile: 128 keys x 128 d fp16 for K and V = 2 x 32KB
    auto load_tile = [&](int jt, int buf) {
        const size_t k0 = (size_t)jt * BK2;
#pragma unroll
        for (int r = 0; r < 8; r++) {
            int idx = tid + r * 256;
            int k = idx >> 4, ch = idx & 15;
            uint32_t off = buf * ABUF + (uint32_t)k * PITCH + ch * 16;
            const size_t g = (k0 + k) * O_ + ch * 8;
            CP16(sb + AK_OFF + off, Ph + g);
            CP16(sb + AV_OFF + off, Vh + g);
        }
    };

    load_tile(0, 0);
    CP_COMMIT();

    for (int j = 0; j < NT2; j++) {
        const int buf = j & 1;
        if (j + 1 < NT2) { load_tile(j + 1, buf ^ 1); CP_COMMIT(); CP_WAIT1(); }
        else            { CP_WAIT0(); }
        __syncthreads();

        // S = Q K^T : 16 q-rows x 128 keys per warp
        float S[16][4];
#pragma unroll
        for (int jb = 0; jb < 16; jb++)
#pragma unroll
            for (int i = 0; i < 4; i++) S[jb][i] = 0.f;
        const uint32_t kb = kb4 + buf * ABUF;
#pragma unroll
        for (int s = 0; s < 8; s++) {
#pragma unroll
            for (int jb2 = 0; jb2 < 8; jb2++) {
                uint32_t b0, b1, b2, b3;
                LDSM4(b0, b1, b2, b3, kb + jb2 * (16 * PITCH) + s * 32);
                MMAF16(S[2 * jb2],     qh[s], b0, b1);
                MMAF16(S[2 * jb2 + 1], qh[s], b2, b3);
            }
        }

        // running max (branchless rescale)
        float mt0 = S[0][0], mt1 = S[0][2];
#pragma unroll
        for (int jb = 0; jb < 16; jb++) {
            mt0 = fmaxf(mt0, fmaxf(S[jb][0], S[jb][1]));
            mt1 = fmaxf(mt1, fmaxf(S[jb][2], S[jb][3]));
        }
        mt0 = fmaxf(mt0, __shfl_xor_sync(0xffffffffu, mt0, 1));
        mt0 = fmaxf(mt0, __shfl_xor_sync(0xffffffffu, mt0, 2));
        mt1 = fmaxf(mt1, __shfl_xor_sync(0xffffffffu, mt1, 1));
        mt1 = fmaxf(mt1, __shfl_xor_sync(0xffffffffu, mt1, 2));
        float m0n = fmaxf(m0, mt0), m1n = fmaxf(m1, mt1);
        float sc0 = __expf(m0 - m0n), sc1 = __expf(m1 - m1n);
        m0 = m0n; m1 = m1n;
        l0 *= sc0; l1 *= sc1;
#pragma unroll
        for (int t = 0; t < 16; t++) {
            acc[t][0] *= sc0; acc[t][1] *= sc0;
            acc[t][2] *= sc1; acc[t][3] *= sc1;
        }

        // P = exp(S - m) fp16; sum rounded values
        uint32_t ah[8][4];
#pragma unroll
        for (int jb = 0; jb < 16; jb++) {
            float p0 = __expf(S[jb][0] - m0), p1 = __expf(S[jb][1] - m0);
            float p2 = __expf(S[jb][2] - m1), p3 = __expf(S[jb][3] - m1);
            uint32_t pk0 = h2pair(p0, p1), pk2 = h2pair(p2, p3);
            __half2 f0 = *(__half2*)&pk0, f2 = *(__half2*)&pk2;
            l0 += __low2float(f0) + __high2float(f0);
            l1 += __low2float(f2) + __high2float(f2);
            ah[jb >> 1][(jb & 1) * 2]     = pk0;
            ah[jb >> 1][(jb & 1) * 2 + 1] = pk2;
        }

        // acc += P @ V  (k = 128 keys)
        const uint32_t vb = vb4 + buf * ABUF;
#pragma unroll
        for (int s2 = 0; s2 < 8; s2++) {
#pragma unroll
            for (int t2 = 0; t2 < 8; t2++) {
                uint32_t v0, v1, v2, v3;
                LDSM4T(v0, v1, v2, v3, vb + s2 * (16 * PITCH) + t2 * 32);
                MMAF16(acc[2 * t2],     ah[s2], v0, v1);
                MMAF16(acc[2 * t2 + 1], ah[s2], v2, v3);
            }
        }
        __syncthreads();
    }

    // epilogue
    l0 += __shfl_xor_sync(0xffffffffu, l0, 1);
    l0 += __shfl_xor_sync(0xffffffffu, l0, 2);
    l1 += __shfl_xor_sync(0xffffffffu, l1, 1);
    l1 += __shfl_xor_sync(0xffffffffu, l1, 2);
    const float inv0 = 1.f / l0, inv1 = 1.f / l1;

    const size_t row0 = (size_t)b * N_ + q0 + wid * 16 + (lane >> 2);
#pragma unroll
    for (int t = 0; t < 16; t++) {
        const int o = t * 8 + 2 * (lane & 3);
        *(uint32_t*)(d_y16 + row0 * O_ + o)       = h2pair(acc[t][0] * inv0, acc[t][1] * inv0);
        *(uint32_t*)(d_y16 + (row0 + 8) * O_ + o) = h2pair(acc[t][2] * inv1, acc[t][3] * inv1);
    }
}

// ---------------------------------------------------------------------------
// Kernel 3: out = x + BN(W_out y + b_out), single fp16 GEMM.
// ---------------------------------------------------------------------------
#define OK_WH 0
#define OK_YH 34816
#define OUT_SMEM 69632

__global__ __launch_bounds__(256, 1) void out_kernel(
    const float* __restrict__ x,
    const float* __restrict__ wo, const float* __restrict__ bo,
    const float* __restrict__ gamma, const float* __restrict__ beta,
    const float* __restrict__ mean, const float* __restrict__ var,
    float* __restrict__ out)
{
    extern __shared__ __align__(128) char smem[];
    const uint32_t sb = smem_u32(smem);
    const int tid = threadIdx.x;
    const int wid = tid >> 5, lane = tid & 31;
    const int b = blockIdx.z, c0 = blockIdx.y * 128, n0 = blockIdx.x * 128;

#pragma unroll
    for (int r = 0; r < 4; r++) {
        int idx = tid + r * 256;
        int row = idx >> 3, ch = idx & 7;
        const size_t g = ((size_t)b * N_ + n0 + row) * O_ + ch * 16;
        uint32_t off = (uint32_t)row * PITCH + ch * 32;
        CP16(sb + OK_YH + off,      d_y16 + g);
        CP16(sb + OK_YH + off + 16, d_y16 + g + 8);
    }
    CP_COMMIT();

#pragma unroll
    for (int r = 0; r < 16; r++) {
        int idx = tid + r * 256;
        int c = idx >> 5, ov = (idx & 31) << 2;
        float4 w = *(const float4*)(wo + (size_t)(c0 + c) * O_ + ov);
        uint32_t off = (uint32_t)c * PITCH + ov * 2;
        *(uint32_t*)(smem + OK_WH + off)     = h2pair(w.x, w.y);
        *(uint32_t*)(smem + OK_WH + off + 4) = h2pair(w.z, w.w);
    }
    CP_WAIT0();
    __syncthreads();

    float acc[16][4];
#pragma unroll
    for (int t = 0; t < 16; t++)
#pragma unroll
        for (int i = 0; i < 4; i++) acc[t][i] = 0.f;

    const uint32_t wa  = sb + OK_WH + (uint32_t)(wid * 16 + (lane & 15)) * PITCH + ((lane >> 4) & 1) * 16;
    const uint32_t yb4 = sb + OK_YH + (lane & 7) * PITCH + ((lane >> 3) & 1) * 16
                       + (lane >> 4) * (8 * PITCH);

#pragma unroll
    for (int s = 0; s < 8; s++) {
        uint32_t ahf[4];
        LDSM4(ahf[0], ahf[1], ahf[2], ahf[3], wa + s * 32);
#pragma unroll
        for (int jb2 = 0; jb2 < 8; jb2++) {
            uint32_t y0, y1, y2, y3;
            LDSM4(y0, y1, y2, y3, yb4 + jb2 * (16 * PITCH) + s * 32);
            MMAF16(acc[2 * jb2],     ahf, y0, y1);
            MMAF16(acc[2 * jb2 + 1], ahf, y2, y3);
        }
    }

    const int cr0 = c0 + wid * 16 + (lane >> 2);
#pragma unroll
    for (int h = 0; h < 2; h++) {
        const int c = cr0 + h * 8;
        const float inv = gamma[c] * rsqrtf(var[c] + 1e-5f);
        const float sh = beta[c] - mean[c] * inv + bo[c] * inv;
        const size_t rb = ((size_t)(b * C_ + c)) * N_ + n0 + 2 * (lane & 3);
#pragma unroll
        for (int jb = 0; jb < 16; jb++) {
            float2 xv = *(const float2*)(x + rb + jb * 8);
            float2 ov;
            ov.x = xv.x + acc[jb][2 * h + 0] * inv + sh;
            ov.y = xv.y + acc[jb][2 * h + 1] * inv + sh;
            *(float2*)(out + rb + jb * 8) = ov;
        }
    }
}

// ---------------------------------------------------------------------------
extern "C" void kernel_launch(void* const* d_in, const int* in_sizes, int n_in,
                              void* d_out, int out_size)
{
    const float* x     = (const float*)d_in[0];
    const float* wt    = (const float*)d_in[1];
    const float* bt    = (const float*)d_in[2];
    const float* wp    = (const float*)d_in[3];
    const float* bp    = (const float*)d_in[4];
    const float* wg    = (const float*)d_in[5];
    const float* bg    = (const float*)d_in[6];
    const float* wo    = (const float*)d_in[7];
    const float* bo    = (const float*)d_in[8];
    const float* gamma = (const float*)d_in[9];
    const float* beta  = (const float*)d_in[10];
    const float* mean  = (const float*)d_in[11];
    const float* var   = (const float*)d_in[12];
    float* out = (float*)d_out;

    cudaFuncSetAttribute(proj_kernel, cudaFuncAttributeMaxDynamicSharedMemorySize, PROJ_SMEM);
    cudaFuncSetAttribute(attn_kernel, cudaFuncAttributeMaxDynamicSharedMemorySize, ATTN_SMEM);
    cudaFuncSetAttribute(out_kernel,  cudaFuncAttributeMaxDynamicSharedMemorySize, OUT_SMEM);

    setup_kernel<<<3, 256>>>(wt, wp, wg);
    proj_kernel<<<dim3(32, 8, 3), 256, PROJ_SMEM>>>(x, bt, bp, bg);
    attn_kernel<<<dim3(32, 8), 256, ATTN_SMEM>>>();
    out_kernel<<<dim3(32, 2, 8), 256, OUT_SMEM>>>(x, wo, bo, gamma, beta, mean, var, out);
}

// round 10
// speedup vs baseline: 7.0791x; 1.1118x over previous
#include <cuda_runtime.h>
#include <cuda_fp16.h>
#include <cstdint>
#include <math.h>

#define B_ 8
#define C_ 256
#define N_ 4096
#define O_ 128

// Scratch (__device__ globals: allocation-free rule).
__device__ __half d_th [(size_t)B_ * N_ * O_];   // theta * log2(e), fp16
__device__ __half d_ph [(size_t)B_ * N_ * O_];
__device__ __half d_g  [(size_t)B_ * N_ * O_];
__device__ __half d_y16[(size_t)B_ * N_ * O_];
__device__ __half d_w16[3 * O_ * C_];

__device__ __forceinline__ uint32_t smem_u32(const void* p) {
    uint32_t a;
    asm("{ .reg .u64 t; cvta.to.shared.u64 t, %1; cvt.u32.u64 %0, t; }" : "=r"(a) : "l"(p));
    return a;
}

#define MMAF16(c, a, b0v, b1v) asm volatile( \
    "mma.sync.aligned.m16n8k16.row.col.f32.f16.f16.f32 " \
    "{%0,%1,%2,%3}, {%4,%5,%6,%7}, {%8,%9}, {%0,%1,%2,%3};" \
    : "+f"((c)[0]), "+f"((c)[1]), "+f"((c)[2]), "+f"((c)[3]) \
    : "r"((a)[0]), "r"((a)[1]), "r"((a)[2]), "r"((a)[3]), "r"(b0v), "r"(b1v))

// fp16-accumulator MMA (C/D are 2 x fp16x2 regs)
#define MMAH(c, a, b0v, b1v) asm volatile( \
    "mma.sync.aligned.m16n8k16.row.col.f16.f16.f16.f16 " \
    "{%0,%1}, {%2,%3,%4,%5}, {%6,%7}, {%0,%1};" \
    : "+r"((c)[0]), "+r"((c)[1]) \
    : "r"((a)[0]), "r"((a)[1]), "r"((a)[2]), "r"((a)[3]), "r"(b0v), "r"(b1v))

#define LDSM4(r0, r1, r2, r3, addr)  asm volatile("ldmatrix.sync.aligned.m8n8.x4.shared.b16 {%0,%1,%2,%3}, [%4];" : "=r"(r0), "=r"(r1), "=r"(r2), "=r"(r3) : "r"(addr))
#define LDSM4T(r0, r1, r2, r3, addr) asm volatile("ldmatrix.sync.aligned.m8n8.x4.trans.shared.b16 {%0,%1,%2,%3}, [%4];" : "=r"(r0), "=r"(r1), "=r"(r2), "=r"(r3) : "r"(addr))
#define CP16(dst, src)   asm volatile("cp.async.cg.shared.global [%0], [%1], 16;" :: "r"(dst), "l"(src))
#define CP_COMMIT()      asm volatile("cp.async.commit_group;" ::: "memory")
#define CP_WAIT0()       asm volatile("cp.async.wait_group 0;" ::: "memory")
#define CP_WAIT1()       asm volatile("cp.async.wait_group 1;" ::: "memory")
#define EX2H2(r)         asm("ex2.approx.f16x2 %0, %0;" : "+r"(r))
#define HMUL2(d, s)      asm("mul.rn.f16x2 %0, %0, %1;" : "+r"(d) : "r"(s))

__device__ __forceinline__ uint32_t h2pair(float a, float b) {
    uint32_t r;
    asm("cvt.rn.f16x2.f32 %0, %1, %2;" : "=r"(r) : "f"(b), "f"(a));
    return r;
}

#define PITCH 272
#define LOG2E 1.4426950408889634f
#define ONESH2 0x3C003C00u

// ---------------------------------------------------------------------------
// Kernel 0: W -> fp16 once.
// ---------------------------------------------------------------------------
__global__ void setup_kernel(const float* __restrict__ wt,
                             const float* __restrict__ wp,
                             const float* __restrict__ wg)
{
    const int z = blockIdx.x;
    const float* W = (z == 0) ? wt : (z == 1) ? wp : wg;
    __half* out = d_w16 + (size_t)z * O_ * C_;
    for (int i = threadIdx.x; i < O_ * C_ / 4; i += blockDim.x) {
        float4 w = *(const float4*)(W + i * 4);
        *(uint32_t*)(out + i * 4)     = h2pair(w.x, w.y);
        *(uint32_t*)(out + i * 4 + 2) = h2pair(w.z, w.w);
    }
}

// ---------------------------------------------------------------------------
// Kernel 1: projections, single fp16 GEMM.  theta gets *LOG2E.
// grid (32 n, 8 b, 3 z), 256 thr.
// ---------------------------------------------------------------------------
#define PJ_WH 0
#define PJ_X  67584
#define PJ_XBUF 8704
#define PJ_PW 528
#define PROJ_SMEM 84992

__global__ __launch_bounds__(256, 1) void proj_kernel(
    const float* __restrict__ x,
    const float* __restrict__ bt, const float* __restrict__ bp,
    const float* __restrict__ bg)
{
    extern __shared__ __align__(128) char smem[];
    const uint32_t sb = smem_u32(smem);
    const int tid = threadIdx.x;
    const int wid = tid >> 5, lane = tid & 31;
    const int b = blockIdx.y, n0 = blockIdx.x * 128, z = blockIdx.z;
    const float* bias = (z == 0) ? bt : (z == 1) ? bp : bg;
    __half* outp = (z == 0) ? d_th : (z == 1) ? d_ph : d_g;
    const __half* Wg = d_w16 + (size_t)z * O_ * C_;
    const float osc = (z == 0) ? LOG2E : 1.f;

#pragma unroll
    for (int r = 0; r < 16; r++) {
        int idx = tid + r * 256;
        int o = idx >> 5, ch = idx & 31;
        CP16(sb + PJ_WH + (uint32_t)o * PJ_PW + ch * 16, Wg + (size_t)o * C_ + ch * 8);
    }
    CP_COMMIT();

    float4 xr[4];
    auto ldg_chunk = [&](int ck) {
#pragma unroll
        for (int r = 0; r < 4; r++) {
            int idx = tid + r * 256;
            int cc = idx >> 5, nv = (idx & 31) << 2;
            xr[r] = *(const float4*)(x + ((size_t)(b * C_ + ck * 32 + cc)) * N_ + n0 + nv);
        }
    };
    auto sts_chunk = [&](int buf) {
#pragma unroll
        for (int r = 0; r < 4; r++) {
            int idx = tid + r * 256;
            int cc = idx >> 5, nv = (idx & 31) << 2;
            float4 v = xr[r];
            uint32_t base = PJ_X + buf * PJ_XBUF + (uint32_t)cc * PITCH + nv * 2;
            *(uint32_t*)(smem + base)     = h2pair(v.x, v.y);
            *(uint32_t*)(smem + base + 4) = h2pair(v.z, v.w);
        }
    };

    ldg_chunk(0);
    CP_WAIT0();
    sts_chunk(0);
    __syncthreads();

    float acc[16][4];
#pragma unroll
    for (int t = 0; t < 16; t++)
#pragma unroll
        for (int i = 0; i < 4; i++) acc[t][i] = 0.f;

    const uint32_t xa_off = (uint32_t)((lane & 7) + ((lane >> 4) << 3)) * PITCH
                          + (uint32_t)(wid * 16 + (((lane >> 3) & 1) << 3)) * 2;
    const uint32_t wb4 = (uint32_t)(lane & 7) * PJ_PW + ((lane >> 3) & 1) * 16
                       + (uint32_t)(lane >> 4) * (8 * PJ_PW);

    for (int ck = 0; ck < 8; ck++) {
        const int buf = ck & 1;
        if (ck < 7) ldg_chunk(ck + 1);
        const uint32_t xb = sb + PJ_X + buf * PJ_XBUF + xa_off;
#pragma unroll
        for (int s = 0; s < 2; s++) {
            uint32_t ah[4];
            LDSM4T(ah[0], ah[1], ah[2], ah[3], xb + s * (16 * PITCH));
            const uint32_t wcol = sb + PJ_WH + wb4 + (uint32_t)(ck * 32 + s * 16) * 2;
#pragma unroll
            for (int jb2 = 0; jb2 < 8; jb2++) {
                uint32_t b0, b1, b2, b3;
                LDSM4(b0, b1, b2, b3, wcol + jb2 * (16 * PJ_PW));
                MMAF16(acc[2 * jb2],     ah, b0, b1);
                MMAF16(acc[2 * jb2 + 1], ah, b2, b3);
            }
        }
        if (ck < 7) sts_chunk(buf ^ 1);
        __syncthreads();
    }

    const size_t row0 = (size_t)b * N_ + n0 + wid * 16 + (lane >> 2);
#pragma unroll
    for (int jb = 0; jb < 16; jb++) {
        const int o = jb * 8 + 2 * (lane & 3);
        float2 b2 = *(const float2*)(bias + o);
        *(uint32_t*)(outp + row0 * O_ + o)       = h2pair((acc[jb][0] + b2.x) * osc, (acc[jb][1] + b2.y) * osc);
        *(uint32_t*)(outp + (row0 + 8) * O_ + o) = h2pair((acc[jb][2] + b2.x) * osc, (acc[jb][3] + b2.y) * osc);
    }
}

// ---------------------------------------------------------------------------
// Kernel 2: fp16 flash attention, BM=256, BK=64, 8 warps x 32 q-rows.
// QK fp32-acc; softmax base-2 (ex2.f16x2); l via ones-MMA; PV fp16-acc.
// grid (16 q-tiles, 8 b), 256 threads. 1 wave of 128 CTAs.
// ---------------------------------------------------------------------------
#define BKA 64
#define NTA (N_ / BKA)
#define AK_OFF 0
#define AV_OFF 17408
#define ABUF   34816
#define ATTN_SMEM 69632

__global__ __launch_bounds__(256, 1) void attn_kernel()
{
    extern __shared__ __align__(128) char smem[];
    const uint32_t sb = smem_u32(smem);
    const int tid = threadIdx.x;
    const int wid = tid >> 5, lane = tid & 31;
    const int b = blockIdx.y, q0 = blockIdx.x * 256;

    // Q fragments: 2 M-blocks x 8 k-steps (theta already *log2e)
    uint32_t qh[2][8][4];
#pragma unroll
    for (int mb = 0; mb < 2; mb++) {
        const __half* Th = d_th + ((size_t)b * N_ + q0 + wid * 32 + mb * 16 + (lane >> 2)) * O_;
        const int c0 = 2 * (lane & 3);
#pragma unroll
        for (int s = 0; s < 8; s++) {
            qh[mb][s][0] = *(const uint32_t*)(Th + s * 16 + c0);
            qh[mb][s][1] = *(const uint32_t*)(Th + 8 * O_ + s * 16 + c0);
            qh[mb][s][2] = *(const uint32_t*)(Th + s * 16 + c0 + 8);
            qh[mb][s][3] = *(const uint32_t*)(Th + 8 * O_ + s * 16 + c0 + 8);
        }
    }

    const __half* Ph = d_ph + (size_t)b * N_ * O_;
    const __half* Vh = d_g  + (size_t)b * N_ * O_;

    const uint32_t kb4 = sb + AK_OFF + (lane & 7) * PITCH + ((lane >> 3) & 1) * 16
                       + (lane >> 4) * (8 * PITCH);
    const uint32_t vb4 = sb + AV_OFF + (lane & 7) * PITCH + ((lane >> 3) & 1) * (8 * PITCH)
                       + (lane >> 4) * 16;

    uint32_t acc2[2][16][2];   // fp16x2 accumulators
#pragma unroll
    for (int mb = 0; mb < 2; mb++)
#pragma unroll
        for (int k = 0; k < 16; k++) { acc2[mb][k][0] = 0u; acc2[mb][k][1] = 0u; }
    float lacc[2][4];
#pragma unroll
    for (int mb = 0; mb < 2; mb++)
#pragma unroll
        for (int i = 0; i < 4; i++) lacc[mb][i] = 0.f;
    float m0[2] = {-1e30f, -1e30f}, m1[2] = {-1e30f, -1e30f};

    auto load_tile = [&](int jt, int buf) {
        const size_t k0 = (size_t)jt * BKA;
#pragma unroll
        for (int r = 0; r < 4; r++) {
            int idx = tid + r * 256;
            int k = idx >> 4, ch = idx & 15;
            uint32_t off = buf * ABUF + (uint32_t)k * PITCH + ch * 16;
            const size_t g = (k0 + k) * O_ + ch * 8;
            CP16(sb + AK_OFF + off, Ph + g);
            CP16(sb + AV_OFF + off, Vh + g);
        }
    };

    load_tile(0, 0);
    CP_COMMIT();

    for (int j = 0; j < NTA; j++) {
        const int buf = j & 1;
        if (j + 1 < NTA) { load_tile(j + 1, buf ^ 1); CP_COMMIT(); CP_WAIT1(); }
        else            { CP_WAIT0(); }
        __syncthreads();

        // S = Q K^T, fp32 acc (base-2 logits).  S[mb*8+nb]
        float S[16][4];
#pragma unroll
        for (int i = 0; i < 16; i++)
#pragma unroll
            for (int q = 0; q < 4; q++) S[i][q] = 0.f;
        const uint32_t kb = kb4 + buf * ABUF;
#pragma unroll
        for (int s = 0; s < 8; s++) {
#pragma unroll
            for (int jb2 = 0; jb2 < 4; jb2++) {
                uint32_t b0, b1, b2, b3;
                LDSM4(b0, b1, b2, b3, kb + jb2 * (16 * PITCH) + s * 32);
                MMAF16(S[2 * jb2],         qh[0][s], b0, b1);
                MMAF16(S[2 * jb2 + 1],     qh[0][s], b2, b3);
                MMAF16(S[8 + 2 * jb2],     qh[1][s], b0, b1);
                MMAF16(S[8 + 2 * jb2 + 1], qh[1][s], b2, b3);
            }
        }

        // softmax (base 2), per M-block
        uint32_t ah[2][4][4];
#pragma unroll
        for (int mb = 0; mb < 2; mb++) {
            float mt0 = S[mb * 8][0], mt1 = S[mb * 8][2];
#pragma unroll
            for (int nb = 0; nb < 8; nb++) {
                mt0 = fmaxf(mt0, fmaxf(S[mb * 8 + nb][0], S[mb * 8 + nb][1]));
                mt1 = fmaxf(mt1, fmaxf(S[mb * 8 + nb][2], S[mb * 8 + nb][3]));
            }
            mt0 = fmaxf(mt0, __shfl_xor_sync(0xffffffffu, mt0, 1));
            mt0 = fmaxf(mt0, __shfl_xor_sync(0xffffffffu, mt0, 2));
            mt1 = fmaxf(mt1, __shfl_xor_sync(0xffffffffu, mt1, 1));
            mt1 = fmaxf(mt1, __shfl_xor_sync(0xffffffffu, mt1, 2));
            float mn0 = fmaxf(m0[mb], mt0), mn1 = fmaxf(m1[mb], mt1);
            float sc0 = exp2f(m0[mb] - mn0), sc1 = exp2f(m1[mb] - mn1);
            m0[mb] = mn0; m1[mb] = mn1;
            uint32_t scp0 = h2pair(sc0, sc0), scp1 = h2pair(sc1, sc1);
#pragma unroll
            for (int k = 0; k < 16; k++) {
                HMUL2(acc2[mb][k][0], scp0);
                HMUL2(acc2[mb][k][1], scp1);
            }
            lacc[mb][0] *= sc0; lacc[mb][1] *= sc0;
            lacc[mb][2] *= sc1; lacc[mb][3] *= sc1;
#pragma unroll
            for (int nb = 0; nb < 8; nb++) {
                const int i = mb * 8 + nb;
                uint32_t p0 = h2pair(S[i][0] - mn0, S[i][1] - mn0);
                uint32_t p1 = h2pair(S[i][2] - mn1, S[i][3] - mn1);
                EX2H2(p0);
                EX2H2(p1);
                ah[mb][nb >> 1][(nb & 1) * 2]     = p0;
                ah[mb][nb >> 1][(nb & 1) * 2 + 1] = p1;
            }
        }

        // PV (fp16 acc) + row sums via ones-MMA (fp32 acc)
        const uint32_t vb = vb4 + buf * ABUF;
#pragma unroll
        for (int s2 = 0; s2 < 4; s2++) {
            MMAF16(lacc[0], ah[0][s2], ONESH2, ONESH2);
            MMAF16(lacc[1], ah[1][s2], ONESH2, ONESH2);
#pragma unroll
            for (int t2 = 0; t2 < 8; t2++) {
                uint32_t v0, v1, v2, v3;
                LDSM4T(v0, v1, v2, v3, vb + s2 * (16 * PITCH) + t2 * 32);
                MMAH(acc2[0][2 * t2],     ah[0][s2], v0, v1);
                MMAH(acc2[0][2 * t2 + 1], ah[0][s2], v2, v3);
                MMAH(acc2[1][2 * t2],     ah[1][s2], v0, v1);
                MMAH(acc2[1][2 * t2 + 1], ah[1][s2], v2, v3);
            }
        }
        __syncthreads();
    }

    // epilogue: normalize by l (from ones-MMA), store y fp16
#pragma unroll
    for (int mb = 0; mb < 2; mb++) {
        const float inv0 = 1.f / lacc[mb][0];
        const float inv1 = 1.f / lacc[mb][2];
        const size_t row = (size_t)b * N_ + q0 + wid * 32 + mb * 16 + (lane >> 2);
#pragma unroll
        for (int k = 0; k < 16; k++) {
            const int col = (k >> 1) * 16 + (k & 1) * 8 + 2 * (lane & 3);
            __half2 h0 = *(__half2*)&acc2[mb][k][0];
            __half2 h1 = *(__half2*)&acc2[mb][k][1];
            *(uint32_t*)(d_y16 + row * O_ + col) =
                h2pair(__low2float(h0) * inv0, __high2float(h0) * inv0);
            *(uint32_t*)(d_y16 + (row + 8) * O_ + col) =
                h2pair(__low2float(h1) * inv1, __high2float(h1) * inv1);
        }
    }
}

// ---------------------------------------------------------------------------
// Kernel 3: out = x + BN(W_out y + b_out), single fp16 GEMM.
// ---------------------------------------------------------------------------
#define OK_WH 0
#define OK_YH 34816
#define OUT_SMEM 69632

__global__ __launch_bounds__(256, 1) void out_kernel(
    const float* __restrict__ x,
    const float* __restrict__ wo, const float* __restrict__ bo,
    const float* __restrict__ gamma, const float* __restrict__ beta,
    const float* __restrict__ mean, const float* __restrict__ var,
    float* __restrict__ out)
{
    extern __shared__ __align__(128) char smem[];
    const uint32_t sb = smem_u32(smem);
    const int tid = threadIdx.x;
    const int wid = tid >> 5, lane = tid & 31;
    const int b = blockIdx.z, c0 = blockIdx.y * 128, n0 = blockIdx.x * 128;

#pragma unroll
    for (int r = 0; r < 4; r++) {
        int idx = tid + r * 256;
        int row = idx >> 3, ch = idx & 7;
        const size_t g = ((size_t)b * N_ + n0 + row) * O_ + ch * 16;
        uint32_t off = (uint32_t)row * PITCH + ch * 32;
        CP16(sb + OK_YH + off,      d_y16 + g);
        CP16(sb + OK_YH + off + 16, d_y16 + g + 8);
    }
    CP_COMMIT();

#pragma unroll
    for (int r = 0; r < 16; r++) {
        int idx = tid + r * 256;
        int c = idx >> 5, ov = (idx & 31) << 2;
        float4 w = *(const float4*)(wo + (size_t)(c0 + c) * O_ + ov);
        uint32_t off = (uint32_t)c * PITCH + ov * 2;
        *(uint32_t*)(smem + OK_WH + off)     = h2pair(w.x, w.y);
        *(uint32_t*)(smem + OK_WH + off + 4) = h2pair(w.z, w.w);
    }
    CP_WAIT0();
    __syncthreads();

    float acc[16][4];
#pragma unroll
    for (int t = 0; t < 16; t++)
#pragma unroll
        for (int i = 0; i < 4; i++) acc[t][i] = 0.f;

    const uint32_t wa  = sb + OK_WH + (uint32_t)(wid * 16 + (lane & 15)) * PITCH + ((lane >> 4) & 1) * 16;
    const uint32_t yb4 = sb + OK_YH + (lane & 7) * PITCH + ((lane >> 3) & 1) * 16
                       + (lane >> 4) * (8 * PITCH);

#pragma unroll
    for (int s = 0; s < 8; s++) {
        uint32_t ahf[4];
        LDSM4(ahf[0], ahf[1], ahf[2], ahf[3], wa + s * 32);
#pragma unroll
        for (int jb2 = 0; jb2 < 8; jb2++) {
            uint32_t y0, y1, y2, y3;
            LDSM4(y0, y1, y2, y3, yb4 + jb2 * (16 * PITCH) + s * 32);
            MMAF16(acc[2 * jb2],     ahf, y0, y1);
            MMAF16(acc[2 * jb2 + 1], ahf, y2, y3);
        }
    }

    const int cr0 = c0 + wid * 16 + (lane >> 2);
#pragma unroll
    for (int h = 0; h < 2; h++) {
        const int c = cr0 + h * 8;
        const float inv = gamma[c] * rsqrtf(var[c] + 1e-5f);
        const float sh = beta[c] - mean[c] * inv + bo[c] * inv;
        const size_t rb = ((size_t)(b * C_ + c)) * N_ + n0 + 2 * (lane & 3);
#pragma unroll
        for (int jb = 0; jb < 16; jb++) {
            float2 xv = *(const float2*)(x + rb + jb * 8);
            float2 ov;
            ov.x = xv.x + acc[jb][2 * h + 0] * inv + sh;
            ov.y = xv.y + acc[jb][2 * h + 1] * inv + sh;
            *(float2*)(out + rb + jb * 8) = ov;
        }
    }
}

// ---------------------------------------------------------------------------
extern "C" void kernel_launch(void* const* d_in, const int* in_sizes, int n_in,
                              void* d_out, int out_size)
{
    const float* x     = (const float*)d_in[0];
    const float* wt    = (const float*)d_in[1];
    const float* bt    = (const float*)d_in[2];
    const float* wp    = (const float*)d_in[3];
    const float* bp    = (const float*)d_in[4];
    const float* wg    = (const float*)d_in[5];
    const float* bg    = (const float*)d_in[6];
    const float* wo    = (const float*)d_in[7];
    const float* bo    = (const float*)d_in[8];
    const float* gamma = (const float*)d_in[9];
    const float* beta  = (const float*)d_in[10];
    const float* mean  = (const float*)d_in[11];
    const float* var   = (const float*)d_in[12];
    float* out = (float*)d_out;

    cudaFuncSetAttribute(proj_kernel, cudaFuncAttributeMaxDynamicSharedMemorySize, PROJ_SMEM);
    cudaFuncSetAttribute(attn_kernel, cudaFuncAttributeMaxDynamicSharedMemorySize, ATTN_SMEM);
    cudaFuncSetAttribute(out_kernel,  cudaFuncAttributeMaxDynamicSharedMemorySize, OUT_SMEM);

    setup_kernel<<<3, 256>>>(wt, wp, wg);
    proj_kernel<<<dim3(32, 8, 3), 256, PROJ_SMEM>>>(x, bt, bp, bg);
    attn_kernel<<<dim3(16, 8), 256, ATTN_SMEM>>>();
    out_kernel<<<dim3(32, 2, 8), 256, OUT_SMEM>>>(x, wo, bo, gamma, beta, mean, var, out);
}